// round 9
// baseline (speedup 1.0000x reference)
#include <cuda_runtime.h>
#include <cuda_bf16.h>
#include <cstdint>

#define BATCH 64
#define NNODE 50
#define FDIM 64
#define HDIM 128
#define EDGES 2450
#define TSTEPS 40
#define CHUNK 128
#define MAXROWS 896
#define NQ 4
#define NCTA (BATCH*NQ)      // 256
#define NTHR 128

// ---- smem byte offsets ----
#define OFF_W    0           // 4 tiles x 16KB (W1 h0,h1, W2 h0,h1 of current k)
#define OFF_PRE0 65536       // 16384
#define OFF_PRE1 81920       // 16384
#define OFF_Y    98304       // 6400
#define OFF_B1   104704
#define OFF_B2   105728
#define OFF_B3   106752
#define OFF_AGG  107008      // S tile (16x136 bf16) during chunks; agg fp32 after
#define OFF_RT   113664      // 512
#define SMEM_TOTAL 114176

#define SWZ(o) ((o) ^ (((o) >> 3) & 0x70))
#define SSTRIDE 136

// ---------------- device scratch ----------------
__device__ float          g_y[BATCH*NNODE*FDIM];
__device__ float          g_ksum[BATCH*NNODE*FDIM];
__device__ __nv_bfloat16  g_ybf[BATCH*NNODE*FDIM];
__device__ __nv_bfloat16  g_Wt[8*8192];
__device__ int            g_rows[NCTA*MAXROWS];
__device__ int            g_nrows[NCTA];

// ---------------- helpers ----------------
__device__ __forceinline__ void mma16816(float* c, const uint32_t* a, const uint32_t* b) {
    asm volatile(
        "mma.sync.aligned.m16n8k16.row.col.f32.bf16.bf16.f32 "
        "{%0,%1,%2,%3}, {%4,%5,%6,%7}, {%8,%9}, {%0,%1,%2,%3};\n"
        : "+f"(c[0]), "+f"(c[1]), "+f"(c[2]), "+f"(c[3])
        : "r"(a[0]), "r"(a[1]), "r"(a[2]), "r"(a[3]), "r"(b[0]), "r"(b[1]));
}
__device__ __forceinline__ void ldsm4(uint32_t* r, uint32_t addr) {
    asm volatile("ldmatrix.sync.aligned.m8n8.x4.shared.b16 {%0,%1,%2,%3}, [%4];"
                 : "=r"(r[0]), "=r"(r[1]), "=r"(r[2]), "=r"(r[3]) : "r"(addr));
}
__device__ __forceinline__ void ldsm4t(uint32_t* r, uint32_t addr) {
    asm volatile("ldmatrix.sync.aligned.m8n8.x4.trans.shared.b16 {%0,%1,%2,%3}, [%4];"
                 : "=r"(r[0]), "=r"(r[1]), "=r"(r[2]), "=r"(r[3]) : "r"(addr));
}
__device__ __forceinline__ uint32_t smem_u32(const void* p) {
    uint32_t a;
    asm("{ .reg .u64 t; cvta.to.shared.u64 t, %1; cvt.u32.u64 %0, t; }" : "=r"(a) : "l"(p));
    return a;
}
__device__ __forceinline__ uint32_t packbf(float x, float y) {
    __nv_bfloat162 t = __floats2bfloat162_rn(x, y);
    return *reinterpret_cast<uint32_t*>(&t);
}

// ---------------- prep ----------------
__global__ void prep_kernel(const float* __restrict__ fp,
                            const float* __restrict__ W1,
                            const float* __restrict__ W2,
                            float* __restrict__ out) {
    int gsz = gridDim.x * blockDim.x;
    int g0  = blockIdx.x * blockDim.x + threadIdx.x;
    for (int i = g0; i < 4*HDIM*HDIM; i += gsz) {
        int s = i >> 14, rem = i & 16383;
        int n = rem >> 7, k = rem & 127;
        float v = (s < 2) ? W1[s*16384 + k*HDIM + n] : W2[(s-2)*16384 + k*HDIM + n];
        int tile = s*2 + (k >> 6);
        uint32_t boff = (uint32_t)(n*128 + (k & 63)*2);
        g_Wt[tile*8192 + (SWZ(boff) >> 1)] = __float2bfloat16(v);
    }
    for (int i = g0; i < BATCH*NNODE*FDIM; i += gsz) {
        float v = fp[i];
        g_y[i]   = v;
        g_ybf[i] = __float2bfloat16(v);
        out[(i >> 6)*(TSTEPS*FDIM) + (i & 63)] = v;
    }
}

// ---------------- sort ----------------
__global__ void sort_kernel(const int* __restrict__ graph) {
    const int cta = blockIdx.x;
    const int b = cta >> 2, q = cta & 3;
    const int rstart = (q < 2) ? q*13 : 26 + (q-2)*12;
    const int rcnt   = (q < 2) ? 13 : 12;
    const int ebase  = rstart * 49;
    const int ecnt   = rcnt * 49;
    const int lane = threadIdx.x;
    int* rows = g_rows + cta * MAXROWS;
    int row = 0;
#pragma unroll
    for (int k = 0; k < 2; ++k) {
        for (int i0 = 0; i0 < ecnt; i0 += 32) {
            int i = i0 + lane;
            bool m = false; int meta = 0;
            if (i < ecnt) {
                int e = ebase + i;
                int kk = graph[b*EDGES + e];
                int r = e / 49, j = e - r*49;
                int s = j + (j >= r);
                meta = (kk << 16) | (r << 8) | s;
                m = (kk == k);
            }
            unsigned mask = __ballot_sync(0xffffffffu, m);
            if (m) rows[row + __popc(mask & ((1u << lane) - 1u))] = meta;
            row += __popc(mask);
        }
        int pad = (128 - (row & 127)) & 127;
        for (int i = lane; i < pad; i += 32) rows[row + i] = -1;
        row += pad;
    }
    if (lane == 0) g_nrows[cta] = row;
}

// ---------------- fused edge+node kernel: 4 warps, 64x64 tiles ----------------
__global__ void __launch_bounds__(NTHR, 2)
edge_kernel(const float* __restrict__ b1f, const float* __restrict__ b2f,
            const float* __restrict__ W3,  const float* __restrict__ b3f,
            const float* __restrict__ ts,  int t, int stage,
            float* __restrict__ out) {
    extern __shared__ char smb[];
    const int tid  = threadIdx.x;
    const int lane = tid & 31, wid = tid >> 5;     // wid 0..3
    const int cta  = blockIdx.x;
    const int b = cta >> 2, q = cta & 3;
    const int rstart = (q < 2) ? q*13 : 26 + (q-2)*12;
    const int nloc   = (q < 2) ? 13 : 12;

    {
        const uint4* src = reinterpret_cast<const uint4*>(g_ybf + b*NNODE*FDIM);
        uint4* dst = reinterpret_cast<uint4*>(smb + OFF_Y);
        for (int i = tid; i < 6400/16; i += NTHR) dst[i] = src[i];
    }
    for (int i = tid; i < 2*HDIM; i += NTHR) {
        ((float*)(smb + OFF_B1))[i] = b1f[i];
        ((float*)(smb + OFF_B2))[i] = b2f[i];
    }
    if (tid < 64) ((float*)(smb + OFF_B3))[tid] = b3f[tid];

    const float* sB1 = (float*)(smb + OFF_B1);
    const float* sB2 = (float*)(smb + OFF_B2);
    int* sRt = (int*)(smb + OFF_RT);
    __nv_bfloat16* sS = (__nv_bfloat16*)(smb + OFF_AGG);

    const int nch = g_nrows[cta] >> 7;
    const int* __restrict__ rows = g_rows + cta * MAXROWS;

    // warp tiling: 2x2 grid of 64x64 tiles
    const int wm = (wid & 1) * 64;
    const int wn = (wid >> 1) * 64;
    const int g = lane >> 2, tig = lane & 3;
    const int li = lane & 7, lm = lane >> 3;
    const int aRow = (lm & 1)*8 + li;
    const int aK16 = (lm >> 1) * 16;
    const int bRow = (lm >> 1)*8 + li;
    const int bK16 = (lm & 1) * 16;

    const uint32_t uPre0 = smem_u32(smb + OFF_PRE0);
    const uint32_t uPre1 = smem_u32(smb + OFF_PRE1);
    const uint32_t uW    = smem_u32(smb + OFF_W);
    const uint32_t uS    = smem_u32(smb + OFF_AGG);

    // agg-GEMM: warp owns m cols wid*32..wid*32+31
    const uint32_t aggBase = (wid >> 1) ? uPre1 : uPre0;
    const uint32_t aggRowL = (uint32_t)((lm & 1)*8 + li);
    const uint32_t aggColL = (uint32_t)(((wid & 1)*32 + (lm >> 1)*8) * 2);
    const uint32_t sA0 = uS + (uint32_t)(g*(SSTRIDE*2) + 2*tig*2);

    float Ca[4][4];
#pragma unroll
    for (int i = 0; i < 4; ++i) { Ca[i][0]=0.f; Ca[i][1]=0.f; Ca[i][2]=0.f; Ca[i][3]=0.f; }

    int curk = -1;

    for (int ch = 0; ch < nch; ++ch) {
        const int* crow = rows + ch*CHUNK;
        const int k = (crow[0] >> 16);

        if (k != curk) {
            curk = k;
            const uint4* s1 = reinterpret_cast<const uint4*>(g_Wt + (k*2)*8192);
            const uint4* s2 = reinterpret_cast<const uint4*>(g_Wt + ((2 + k)*2)*8192);
            uint4* d1 = reinterpret_cast<uint4*>(smb + OFF_W);
            uint4* d2 = reinterpret_cast<uint4*>(smb + OFF_W + 32768);
            for (int i = tid; i < 2048; i += NTHR) { d1[i] = s1[i]; d2[i] = s2[i]; }
        }

        // zero S tile
        {
            uint32_t* s32 = (uint32_t*)sS;
            for (int i = tid; i < 16*SSTRIDE/2; i += NTHR) s32[i] = 0;
        }
        // gather: one row per thread (both halves) + receiver meta
        {
            int row = tid;
            int v = crow[row];
            sRt[row] = (v < 0) ? -1 : ((v >> 8) & 255);
            if (v >= 0) {
                int nsend = v & 255, nrecv = (v >> 8) & 255;
                const uint4* s0 = (const uint4*)(smb + OFF_Y + nsend*FDIM*2);
                const uint4* s1 = (const uint4*)(smb + OFF_Y + nrecv*FDIM*2);
#pragma unroll
                for (int qq = 0; qq < 8; ++qq) {
                    uint32_t o = SWZ((uint32_t)(row*128 + qq*16));
                    *(uint4*)(smb + OFF_PRE0 + o) = s0[qq];
                    *(uint4*)(smb + OFF_PRE1 + o) = s1[qq];
                }
            } else {
                uint4 z = make_uint4(0,0,0,0);
#pragma unroll
                for (int qq = 0; qq < 8; ++qq) {
                    uint32_t o = SWZ((uint32_t)(row*128 + qq*16));
                    *(uint4*)(smb + OFF_PRE0 + o) = z;
                    *(uint4*)(smb + OFF_PRE1 + o) = z;
                }
            }
        }
        __syncthreads();

        // scatter S ones
        if (tid < 128) {
            int rr = sRt[tid];
            if (rr >= 0) sS[(rr - rstart)*SSTRIDE + tid] = __float2bfloat16(1.0f);
        }

        float C[32][4];

        // ==== GEMM1: C[64x64] = pre @ W1[k]^T ====
#pragma unroll
        for (int i = 0; i < 32; ++i) { C[i][0]=0.f; C[i][1]=0.f; C[i][2]=0.f; C[i][3]=0.f; }
#pragma unroll
        for (int kb = 0; kb < 8; ++kb) {
            const int half = kb >> 2;
            const uint32_t kgrp = (uint32_t)((kb & 3) * 32);
            const uint32_t aBase = half ? uPre1 : uPre0;
            uint32_t a[4][4];
#pragma unroll
            for (int mt = 0; mt < 4; ++mt) {
                uint32_t o = (uint32_t)((wm + mt*16 + aRow)*128) + kgrp + aK16;
                ldsm4(a[mt], aBase + SWZ(o));
            }
            uint32_t bf[4][4];
#pragma unroll
            for (int nt2 = 0; nt2 < 4; ++nt2) {
                uint32_t o = (uint32_t)((wn + nt2*16 + bRow)*128) + kgrp + bK16;
                ldsm4(bf[nt2], uW + half*16384u + SWZ(o));
            }
#pragma unroll
            for (int mt = 0; mt < 4; ++mt)
#pragma unroll
                for (int nt = 0; nt < 8; ++nt)
                    mma16816(C[mt*8 + nt], a[mt], &bf[nt >> 1][(nt & 1)*2]);
        }
        __syncthreads();

        // epilogue1: h = relu(C + b1[k]) -> PRE halves
        {
            const int hh = wn >> 6;
            char* tb = smb + (hh ? OFF_PRE1 : OFF_PRE0);
#pragma unroll
            for (int mt = 0; mt < 4; ++mt)
#pragma unroll
                for (int nt = 0; nt < 8; ++nt) {
                    int r0 = wm + mt*16 + g, r1 = r0 + 8;
                    int c = wn + nt*8 + 2*tig;
                    float b0v = sB1[k*HDIM + c], b1v = sB1[k*HDIM + c + 1];
                    float* x = C[mt*8 + nt];
                    uint32_t cb = (uint32_t)((c & 63)*2);
                    *(uint32_t*)(tb + SWZ((uint32_t)(r0*128) + cb)) =
                        packbf(fmaxf(x[0]+b0v,0.f), fmaxf(x[1]+b1v,0.f));
                    *(uint32_t*)(tb + SWZ((uint32_t)(r1*128) + cb)) =
                        packbf(fmaxf(x[2]+b0v,0.f), fmaxf(x[3]+b1v,0.f));
                }
        }
        __syncthreads();

        // ==== GEMM2: C = h @ W2[k]^T ====
#pragma unroll
        for (int i = 0; i < 32; ++i) { C[i][0]=0.f; C[i][1]=0.f; C[i][2]=0.f; C[i][3]=0.f; }
#pragma unroll
        for (int kb = 0; kb < 8; ++kb) {
            const int half = kb >> 2;
            const uint32_t kgrp = (uint32_t)((kb & 3) * 32);
            const uint32_t aBase = half ? uPre1 : uPre0;
            uint32_t a[4][4];
#pragma unroll
            for (int mt = 0; mt < 4; ++mt) {
                uint32_t o = (uint32_t)((wm + mt*16 + aRow)*128) + kgrp + aK16;
                ldsm4(a[mt], aBase + SWZ(o));
            }
            uint32_t bf[4][4];
#pragma unroll
            for (int nt2 = 0; nt2 < 4; ++nt2) {
                uint32_t o = (uint32_t)((wn + nt2*16 + bRow)*128) + kgrp + bK16;
                ldsm4(bf[nt2], uW + 32768u + half*16384u + SWZ(o));
            }
#pragma unroll
            for (int mt = 0; mt < 4; ++mt)
#pragma unroll
                for (int nt = 0; nt < 8; ++nt)
                    mma16816(C[mt*8 + nt], a[mt], &bf[nt >> 1][(nt & 1)*2]);
        }
        __syncthreads();

        // epilogue2: m = relu(C + b2[k]) -> PRE halves
        {
            const int hh = wn >> 6;
            char* tb = smb + (hh ? OFF_PRE1 : OFF_PRE0);
#pragma unroll
            for (int mt = 0; mt < 4; ++mt)
#pragma unroll
                for (int nt = 0; nt < 8; ++nt) {
                    int r0 = wm + mt*16 + g, r1 = r0 + 8;
                    int c = wn + nt*8 + 2*tig;
                    float b0v = sB2[k*HDIM + c], b1v = sB2[k*HDIM + c + 1];
                    float* x = C[mt*8 + nt];
                    uint32_t cb = (uint32_t)((c & 63)*2);
                    *(uint32_t*)(tb + SWZ((uint32_t)(r0*128) + cb)) =
                        packbf(fmaxf(x[0]+b0v,0.f), fmaxf(x[1]+b1v,0.f));
                    *(uint32_t*)(tb + SWZ((uint32_t)(r1*128) + cb)) =
                        packbf(fmaxf(x[2]+b0v,0.f), fmaxf(x[3]+b1v,0.f));
                }
        }
        __syncthreads();

        // ==== agg GEMM: Ca += S @ m (warp owns m cols wid*32..+31) ====
#pragma unroll
        for (int kb = 0; kb < 8; ++kb) {
            uint32_t a[4];
            uint32_t aoff = sA0 + (uint32_t)(kb*32);
            asm volatile("ld.shared.b32 %0, [%1];" : "=r"(a[0]) : "r"(aoff));
            asm volatile("ld.shared.b32 %0, [%1];" : "=r"(a[1]) : "r"(aoff + 8*(SSTRIDE*2)));
            asm volatile("ld.shared.b32 %0, [%1];" : "=r"(a[2]) : "r"(aoff + 16));
            asm volatile("ld.shared.b32 %0, [%1];" : "=r"(a[3]) : "r"(aoff + 8*(SSTRIDE*2) + 16));
#pragma unroll
            for (int c2 = 0; c2 < 2; ++c2) {
                uint32_t bf[4];
                uint32_t o = (uint32_t)((kb*16 + aggRowL)*128) + aggColL + (uint32_t)(c2*32);
                ldsm4t(bf, aggBase + SWZ(o));
                mma16816(Ca[c2*2],     a, bf);
                mma16816(Ca[c2*2 + 1], a, bf + 2);
            }
        }
        __syncthreads();
    }

    // write register agg to smem (S region reused as fp32 agg [nloc][128])
    {
        float* agg = (float*)(smb + OFF_AGG);
#pragma unroll
        for (int i = 0; i < 4; ++i) {
            int c = wid*32 + i*8 + 2*tig;
            if (g < nloc) {
                agg[g*HDIM + c]     = Ca[i][0];
                agg[g*HDIM + c + 1] = Ca[i][1];
            }
            if (g + 8 < nloc) {
                agg[(g+8)*HDIM + c]     = Ca[i][2];
                agg[(g+8)*HDIM + c + 1] = Ca[i][3];
            }
        }
    }
    __syncthreads();

    // ---- node phase ----
    {
        float* w3 = (float*)(smb + OFF_PRE0);
        for (int i = tid; i < HDIM*FDIM; i += NTHR) w3[i] = W3[i];
    }
    __syncthreads();
    {
        const float dt = ts[t+1] - ts[t];
        const float inv_n = 1.0f / (float)NNODE;
        const float* agg = (float*)(smb + OFF_AGG);
        const float* w3  = (float*)(smb + OFF_PRE0);
        const float* sb3 = (float*)(smb + OFF_B3);
        for (int idx = tid; idx < nloc*FDIM; idx += NTHR) {
            int n = idx >> 6, j = idx & 63;
            const float* ar = agg + n*HDIM;
            float acc = 0.f;
#pragma unroll 8
            for (int h = 0; h < HDIM; ++h)
                acc = fmaf(ar[h], w3[h*FDIM + j], acc);
            float kv = tanhf(acc * inv_n + sb3[j]);
            int gi = (b*NNODE + rstart + n)*FDIM + j;
            float yv = g_y[gi];
            float yin;
            if (stage == 0)      { g_ksum[gi] = kv;        yin = yv + 0.5f*dt*kv; }
            else if (stage == 1) { g_ksum[gi] += 2.f*kv;   yin = yv + 0.5f*dt*kv; }
            else if (stage == 2) { g_ksum[gi] += 2.f*kv;   yin = yv + dt*kv; }
            else {
                float yn = yv + dt*(1.f/6.f)*(g_ksum[gi] + kv);
                g_y[gi] = yn;
                out[(b*NNODE + rstart + n)*(TSTEPS*FDIM) + (t+1)*FDIM + j] = yn;
                yin = yn;
            }
            g_ybf[gi] = __float2bfloat16(yin);
        }
    }
}

// ---------------- launcher ----------------
extern "C" void kernel_launch(void* const* d_in, const int* in_sizes, int n_in,
                              void* d_out, int out_size) {
    const float* fp    = (const float*)d_in[0];
    const float* ts    = (const float*)d_in[1];
    const int*   graph = (const int*)d_in[2];
    const float* W1    = (const float*)d_in[3];
    const float* b1    = (const float*)d_in[4];
    const float* W2    = (const float*)d_in[5];
    const float* b2    = (const float*)d_in[6];
    const float* W3    = (const float*)d_in[7];
    const float* b3    = (const float*)d_in[8];
    float* out = (float*)d_out;

    cudaFuncSetAttribute(edge_kernel, cudaFuncAttributeMaxDynamicSharedMemorySize, SMEM_TOTAL);

    prep_kernel<<<256, 256>>>(fp, W1, W2, out);
    sort_kernel<<<NCTA, 32>>>(graph);
    for (int t = 0; t < TSTEPS - 1; ++t)
        for (int st = 0; st < 4; ++st)
            edge_kernel<<<NCTA, NTHR, SMEM_TOTAL>>>(b1, b2, W3, b3, ts, t, st, out);
}

// round 10
// speedup vs baseline: 1.0007x; 1.0007x over previous
#include <cuda_runtime.h>
#include <cuda_bf16.h>
#include <cstdint>

#define BATCH 64
#define NNODE 50
#define FDIM 64
#define HDIM 128
#define EDGES 2450
#define TSTEPS 40
#define CHUNK 128
#define MAXROWS 896
#define NQ 4
#define NCTA (BATCH*NQ)      // 256
#define NTHR 128

// ---- smem byte offsets ----
#define OFF_W    0           // 4 tiles x 16KB (W1 h0,h1, W2 h0,h1 of current k)
#define OFF_PRE0 65536       // 16384
#define OFF_PRE1 81920       // 16384
#define OFF_Y    98304       // 6400
#define OFF_B1   104704
#define OFF_B2   105728
#define OFF_B3   106752
#define OFF_AGG  107008      // S tile (16x136 bf16) during chunks; agg fp32 after
#define OFF_RT   113664      // 512
#define SMEM_TOTAL 114176

#define SWZ(o) ((o) ^ (((o) >> 3) & 0x70))
#define SSTRIDE 136

// ---------------- device scratch ----------------
__device__ float          g_y[BATCH*NNODE*FDIM];
__device__ float          g_ksum[BATCH*NNODE*FDIM];
__device__ __nv_bfloat16  g_ybf[BATCH*NNODE*FDIM];
__device__ __nv_bfloat16  g_Wt[8*8192];
__device__ int            g_rows[NCTA*MAXROWS];
__device__ int            g_nrows[NCTA];

// ---------------- helpers ----------------
__device__ __forceinline__ void mma16816(float* c, const uint32_t* a, const uint32_t* b) {
    asm volatile(
        "mma.sync.aligned.m16n8k16.row.col.f32.bf16.bf16.f32 "
        "{%0,%1,%2,%3}, {%4,%5,%6,%7}, {%8,%9}, {%0,%1,%2,%3};\n"
        : "+f"(c[0]), "+f"(c[1]), "+f"(c[2]), "+f"(c[3])
        : "r"(a[0]), "r"(a[1]), "r"(a[2]), "r"(a[3]), "r"(b[0]), "r"(b[1]));
}
__device__ __forceinline__ void ldsm4(uint32_t* r, uint32_t addr) {
    asm volatile("ldmatrix.sync.aligned.m8n8.x4.shared.b16 {%0,%1,%2,%3}, [%4];"
                 : "=r"(r[0]), "=r"(r[1]), "=r"(r[2]), "=r"(r[3]) : "r"(addr));
}
__device__ __forceinline__ void ldsm4t(uint32_t* r, uint32_t addr) {
    asm volatile("ldmatrix.sync.aligned.m8n8.x4.trans.shared.b16 {%0,%1,%2,%3}, [%4];"
                 : "=r"(r[0]), "=r"(r[1]), "=r"(r[2]), "=r"(r[3]) : "r"(addr));
}
__device__ __forceinline__ uint32_t smem_u32(const void* p) {
    uint32_t a;
    asm("{ .reg .u64 t; cvta.to.shared.u64 t, %1; cvt.u32.u64 %0, t; }" : "=r"(a) : "l"(p));
    return a;
}
__device__ __forceinline__ uint32_t packbf(float x, float y) {
    __nv_bfloat162 t = __floats2bfloat162_rn(x, y);
    return *reinterpret_cast<uint32_t*>(&t);
}

// ---------------- prep ----------------
__global__ void prep_kernel(const float* __restrict__ fp,
                            const float* __restrict__ W1,
                            const float* __restrict__ W2,
                            float* __restrict__ out) {
    int gsz = gridDim.x * blockDim.x;
    int g0  = blockIdx.x * blockDim.x + threadIdx.x;
    for (int i = g0; i < 4*HDIM*HDIM; i += gsz) {
        int s = i >> 14, rem = i & 16383;
        int n = rem >> 7, k = rem & 127;
        float v = (s < 2) ? W1[s*16384 + k*HDIM + n] : W2[(s-2)*16384 + k*HDIM + n];
        int tile = s*2 + (k >> 6);
        uint32_t boff = (uint32_t)(n*128 + (k & 63)*2);
        g_Wt[tile*8192 + (SWZ(boff) >> 1)] = __float2bfloat16(v);
    }
    for (int i = g0; i < BATCH*NNODE*FDIM; i += gsz) {
        float v = fp[i];
        g_y[i]   = v;
        g_ybf[i] = __float2bfloat16(v);
        out[(i >> 6)*(TSTEPS*FDIM) + (i & 63)] = v;
    }
}

// ---------------- sort ----------------
__global__ void sort_kernel(const int* __restrict__ graph) {
    const int cta = blockIdx.x;
    const int b = cta >> 2, q = cta & 3;
    const int rstart = (q < 2) ? q*13 : 26 + (q-2)*12;
    const int rcnt   = (q < 2) ? 13 : 12;
    const int ebase  = rstart * 49;
    const int ecnt   = rcnt * 49;
    const int lane = threadIdx.x;
    int* rows = g_rows + cta * MAXROWS;
    int row = 0;
#pragma unroll
    for (int k = 0; k < 2; ++k) {
        for (int i0 = 0; i0 < ecnt; i0 += 32) {
            int i = i0 + lane;
            bool m = false; int meta = 0;
            if (i < ecnt) {
                int e = ebase + i;
                int kk = graph[b*EDGES + e];
                int r = e / 49, j = e - r*49;
                int s = j + (j >= r);
                meta = (kk << 16) | (r << 8) | s;
                m = (kk == k);
            }
            unsigned mask = __ballot_sync(0xffffffffu, m);
            if (m) rows[row + __popc(mask & ((1u << lane) - 1u))] = meta;
            row += __popc(mask);
        }
        int pad = (128 - (row & 127)) & 127;
        for (int i = lane; i < pad; i += 32) rows[row + i] = -1;
        row += pad;
    }
    if (lane == 0) g_nrows[cta] = row;
}

// ---------------- fused edge+node kernel: 4 warps, 64x64 tiles ----------------
__global__ void __launch_bounds__(NTHR, 2)
edge_kernel(const float* __restrict__ b1f, const float* __restrict__ b2f,
            const float* __restrict__ W3,  const float* __restrict__ b3f,
            const float* __restrict__ ts,  int t, int stage,
            float* __restrict__ out) {
    extern __shared__ char smb[];
    const int tid  = threadIdx.x;
    const int lane = tid & 31, wid = tid >> 5;     // wid 0..3
    const int cta  = blockIdx.x;
    const int b = cta >> 2, q = cta & 3;
    const int rstart = (q < 2) ? q*13 : 26 + (q-2)*12;
    const int nloc   = (q < 2) ? 13 : 12;

    {
        const uint4* src = reinterpret_cast<const uint4*>(g_ybf + b*NNODE*FDIM);
        uint4* dst = reinterpret_cast<uint4*>(smb + OFF_Y);
        for (int i = tid; i < 6400/16; i += NTHR) dst[i] = src[i];
    }
    for (int i = tid; i < 2*HDIM; i += NTHR) {
        ((float*)(smb + OFF_B1))[i] = b1f[i];
        ((float*)(smb + OFF_B2))[i] = b2f[i];
    }
    if (tid < 64) ((float*)(smb + OFF_B3))[tid] = b3f[tid];

    const float* sB1 = (float*)(smb + OFF_B1);
    const float* sB2 = (float*)(smb + OFF_B2);
    int* sRt = (int*)(smb + OFF_RT);
    __nv_bfloat16* sS = (__nv_bfloat16*)(smb + OFF_AGG);

    const int nch = g_nrows[cta] >> 7;
    const int* __restrict__ rows = g_rows + cta * MAXROWS;

    // warp tiling: 2x2 grid of 64x64 tiles
    const int wm = (wid & 1) * 64;
    const int wn = (wid >> 1) * 64;
    const int g = lane >> 2, tig = lane & 3;
    const int li = lane & 7, lm = lane >> 3;
    const int aRow = (lm & 1)*8 + li;
    const int aK16 = (lm >> 1) * 16;
    const int bRow = (lm >> 1)*8 + li;
    const int bK16 = (lm & 1) * 16;

    const uint32_t uPre0 = smem_u32(smb + OFF_PRE0);
    const uint32_t uPre1 = smem_u32(smb + OFF_PRE1);
    const uint32_t uW    = smem_u32(smb + OFF_W);
    const uint32_t uS    = smem_u32(smb + OFF_AGG);

    // agg-GEMM: warp owns m cols wid*32..wid*32+31
    const uint32_t aggBase = (wid >> 1) ? uPre1 : uPre0;
    const uint32_t aggRowL = (uint32_t)((lm & 1)*8 + li);
    const uint32_t aggColL = (uint32_t)(((wid & 1)*32 + (lm >> 1)*8) * 2);
    const uint32_t sA0 = uS + (uint32_t)(g*(SSTRIDE*2) + 2*tig*2);

    float Ca[4][4];
#pragma unroll
    for (int i = 0; i < 4; ++i) { Ca[i][0]=0.f; Ca[i][1]=0.f; Ca[i][2]=0.f; Ca[i][3]=0.f; }

    int curk = -1;

    for (int ch = 0; ch < nch; ++ch) {
        const int* crow = rows + ch*CHUNK;
        const int k = (crow[0] >> 16);

        if (k != curk) {
            curk = k;
            const uint4* s1 = reinterpret_cast<const uint4*>(g_Wt + (k*2)*8192);
            const uint4* s2 = reinterpret_cast<const uint4*>(g_Wt + ((2 + k)*2)*8192);
            uint4* d1 = reinterpret_cast<uint4*>(smb + OFF_W);
            uint4* d2 = reinterpret_cast<uint4*>(smb + OFF_W + 32768);
            for (int i = tid; i < 2048; i += NTHR) { d1[i] = s1[i]; d2[i] = s2[i]; }
        }

        // zero S tile
        {
            uint32_t* s32 = (uint32_t*)sS;
            for (int i = tid; i < 16*SSTRIDE/2; i += NTHR) s32[i] = 0;
        }
        // gather: one row per thread (both halves) + receiver meta
        {
            int row = tid;
            int v = crow[row];
            sRt[row] = (v < 0) ? -1 : ((v >> 8) & 255);
            if (v >= 0) {
                int nsend = v & 255, nrecv = (v >> 8) & 255;
                const uint4* s0 = (const uint4*)(smb + OFF_Y + nsend*FDIM*2);
                const uint4* s1 = (const uint4*)(smb + OFF_Y + nrecv*FDIM*2);
#pragma unroll
                for (int qq = 0; qq < 8; ++qq) {
                    uint32_t o = SWZ((uint32_t)(row*128 + qq*16));
                    *(uint4*)(smb + OFF_PRE0 + o) = s0[qq];
                    *(uint4*)(smb + OFF_PRE1 + o) = s1[qq];
                }
            } else {
                uint4 z = make_uint4(0,0,0,0);
#pragma unroll
                for (int qq = 0; qq < 8; ++qq) {
                    uint32_t o = SWZ((uint32_t)(row*128 + qq*16));
                    *(uint4*)(smb + OFF_PRE0 + o) = z;
                    *(uint4*)(smb + OFF_PRE1 + o) = z;
                }
            }
        }
        __syncthreads();

        // scatter S ones
        if (tid < 128) {
            int rr = sRt[tid];
            if (rr >= 0) sS[(rr - rstart)*SSTRIDE + tid] = __float2bfloat16(1.0f);
        }

        float C[32][4];

        // ==== GEMM1: C[64x64] = pre @ W1[k]^T ====
#pragma unroll
        for (int i = 0; i < 32; ++i) { C[i][0]=0.f; C[i][1]=0.f; C[i][2]=0.f; C[i][3]=0.f; }
#pragma unroll
        for (int kb = 0; kb < 8; ++kb) {
            const int half = kb >> 2;
            const uint32_t kgrp = (uint32_t)((kb & 3) * 32);
            const uint32_t aBase = half ? uPre1 : uPre0;
            uint32_t a[4][4];
#pragma unroll
            for (int mt = 0; mt < 4; ++mt) {
                uint32_t o = (uint32_t)((wm + mt*16 + aRow)*128) + kgrp + aK16;
                ldsm4(a[mt], aBase + SWZ(o));
            }
            uint32_t bf[4][4];
#pragma unroll
            for (int nt2 = 0; nt2 < 4; ++nt2) {
                uint32_t o = (uint32_t)((wn + nt2*16 + bRow)*128) + kgrp + bK16;
                ldsm4(bf[nt2], uW + half*16384u + SWZ(o));
            }
#pragma unroll
            for (int mt = 0; mt < 4; ++mt)
#pragma unroll
                for (int nt = 0; nt < 8; ++nt)
                    mma16816(C[mt*8 + nt], a[mt], &bf[nt >> 1][(nt & 1)*2]);
        }
        __syncthreads();

        // epilogue1: h = relu(C + b1[k]) -> PRE halves
        {
            const int hh = wn >> 6;
            char* tb = smb + (hh ? OFF_PRE1 : OFF_PRE0);
#pragma unroll
            for (int mt = 0; mt < 4; ++mt)
#pragma unroll
                for (int nt = 0; nt < 8; ++nt) {
                    int r0 = wm + mt*16 + g, r1 = r0 + 8;
                    int c = wn + nt*8 + 2*tig;
                    float b0v = sB1[k*HDIM + c], b1v = sB1[k*HDIM + c + 1];
                    float* x = C[mt*8 + nt];
                    uint32_t cb = (uint32_t)((c & 63)*2);
                    *(uint32_t*)(tb + SWZ((uint32_t)(r0*128) + cb)) =
                        packbf(fmaxf(x[0]+b0v,0.f), fmaxf(x[1]+b1v,0.f));
                    *(uint32_t*)(tb + SWZ((uint32_t)(r1*128) + cb)) =
                        packbf(fmaxf(x[2]+b0v,0.f), fmaxf(x[3]+b1v,0.f));
                }
        }
        __syncthreads();

        // ==== GEMM2: C = h @ W2[k]^T ====
#pragma unroll
        for (int i = 0; i < 32; ++i) { C[i][0]=0.f; C[i][1]=0.f; C[i][2]=0.f; C[i][3]=0.f; }
#pragma unroll
        for (int kb = 0; kb < 8; ++kb) {
            const int half = kb >> 2;
            const uint32_t kgrp = (uint32_t)((kb & 3) * 32);
            const uint32_t aBase = half ? uPre1 : uPre0;
            uint32_t a[4][4];
#pragma unroll
            for (int mt = 0; mt < 4; ++mt) {
                uint32_t o = (uint32_t)((wm + mt*16 + aRow)*128) + kgrp + aK16;
                ldsm4(a[mt], aBase + SWZ(o));
            }
            uint32_t bf[4][4];
#pragma unroll
            for (int nt2 = 0; nt2 < 4; ++nt2) {
                uint32_t o = (uint32_t)((wn + nt2*16 + bRow)*128) + kgrp + bK16;
                ldsm4(bf[nt2], uW + 32768u + half*16384u + SWZ(o));
            }
#pragma unroll
            for (int mt = 0; mt < 4; ++mt)
#pragma unroll
                for (int nt = 0; nt < 8; ++nt)
                    mma16816(C[mt*8 + nt], a[mt], &bf[nt >> 1][(nt & 1)*2]);
        }
        __syncthreads();

        // epilogue2: m = relu(C + b2[k]) -> PRE halves
        {
            const int hh = wn >> 6;
            char* tb = smb + (hh ? OFF_PRE1 : OFF_PRE0);
#pragma unroll
            for (int mt = 0; mt < 4; ++mt)
#pragma unroll
                for (int nt = 0; nt < 8; ++nt) {
                    int r0 = wm + mt*16 + g, r1 = r0 + 8;
                    int c = wn + nt*8 + 2*tig;
                    float b0v = sB2[k*HDIM + c], b1v = sB2[k*HDIM + c + 1];
                    float* x = C[mt*8 + nt];
                    uint32_t cb = (uint32_t)((c & 63)*2);
                    *(uint32_t*)(tb + SWZ((uint32_t)(r0*128) + cb)) =
                        packbf(fmaxf(x[0]+b0v,0.f), fmaxf(x[1]+b1v,0.f));
                    *(uint32_t*)(tb + SWZ((uint32_t)(r1*128) + cb)) =
                        packbf(fmaxf(x[2]+b0v,0.f), fmaxf(x[3]+b1v,0.f));
                }
        }
        __syncthreads();

        // ==== agg GEMM: Ca += S @ m (warp owns m cols wid*32..+31) ====
#pragma unroll
        for (int kb = 0; kb < 8; ++kb) {
            uint32_t a[4];
            uint32_t aoff = sA0 + (uint32_t)(kb*32);
            asm volatile("ld.shared.b32 %0, [%1];" : "=r"(a[0]) : "r"(aoff));
            asm volatile("ld.shared.b32 %0, [%1];" : "=r"(a[1]) : "r"(aoff + 8*(SSTRIDE*2)));
            asm volatile("ld.shared.b32 %0, [%1];" : "=r"(a[2]) : "r"(aoff + 16));
            asm volatile("ld.shared.b32 %0, [%1];" : "=r"(a[3]) : "r"(aoff + 8*(SSTRIDE*2) + 16));
#pragma unroll
            for (int c2 = 0; c2 < 2; ++c2) {
                uint32_t bf[4];
                uint32_t o = (uint32_t)((kb*16 + aggRowL)*128) + aggColL + (uint32_t)(c2*32);
                ldsm4t(bf, aggBase + SWZ(o));
                mma16816(Ca[c2*2],     a, bf);
                mma16816(Ca[c2*2 + 1], a, bf + 2);
            }
        }
        __syncthreads();
    }

    // write register agg to smem (S region reused as fp32 agg [nloc][128])
    {
        float* agg = (float*)(smb + OFF_AGG);
#pragma unroll
        for (int i = 0; i < 4; ++i) {
            int c = wid*32 + i*8 + 2*tig;
            if (g < nloc) {
                agg[g*HDIM + c]     = Ca[i][0];
                agg[g*HDIM + c + 1] = Ca[i][1];
            }
            if (g + 8 < nloc) {
                agg[(g+8)*HDIM + c]     = Ca[i][2];
                agg[(g+8)*HDIM + c + 1] = Ca[i][3];
            }
        }
    }
    __syncthreads();

    // ---- node phase ----
    {
        float* w3 = (float*)(smb + OFF_PRE0);
        for (int i = tid; i < HDIM*FDIM; i += NTHR) w3[i] = W3[i];
    }
    __syncthreads();
    {
        const float dt = ts[t+1] - ts[t];
        const float inv_n = 1.0f / (float)NNODE;
        const float* agg = (float*)(smb + OFF_AGG);
        const float* w3  = (float*)(smb + OFF_PRE0);
        const float* sb3 = (float*)(smb + OFF_B3);
        for (int idx = tid; idx < nloc*FDIM; idx += NTHR) {
            int n = idx >> 6, j = idx & 63;
            const float* ar = agg + n*HDIM;
            float acc = 0.f;
#pragma unroll 8
            for (int h = 0; h < HDIM; ++h)
                acc = fmaf(ar[h], w3[h*FDIM + j], acc);
            float kv = tanhf(acc * inv_n + sb3[j]);
            int gi = (b*NNODE + rstart + n)*FDIM + j;
            float yv = g_y[gi];
            float yin;
            if (stage == 0)      { g_ksum[gi] = kv;        yin = yv + 0.5f*dt*kv; }
            else if (stage == 1) { g_ksum[gi] += 2.f*kv;   yin = yv + 0.5f*dt*kv; }
            else if (stage == 2) { g_ksum[gi] += 2.f*kv;   yin = yv + dt*kv; }
            else {
                float yn = yv + dt*(1.f/6.f)*(g_ksum[gi] + kv);
                g_y[gi] = yn;
                out[(b*NNODE + rstart + n)*(TSTEPS*FDIM) + (t+1)*FDIM + j] = yn;
                yin = yn;
            }
            g_ybf[gi] = __float2bfloat16(yin);
        }
    }
}

// ---------------- launcher ----------------
extern "C" void kernel_launch(void* const* d_in, const int* in_sizes, int n_in,
                              void* d_out, int out_size) {
    const float* fp    = (const float*)d_in[0];
    const float* ts    = (const float*)d_in[1];
    const int*   graph = (const int*)d_in[2];
    const float* W1    = (const float*)d_in[3];
    const float* b1    = (const float*)d_in[4];
    const float* W2    = (const float*)d_in[5];
    const float* b2    = (const float*)d_in[6];
    const float* W3    = (const float*)d_in[7];
    const float* b3    = (const float*)d_in[8];
    float* out = (float*)d_out;

    cudaFuncSetAttribute(edge_kernel, cudaFuncAttributeMaxDynamicSharedMemorySize, SMEM_TOTAL);

    prep_kernel<<<256, 256>>>(fp, W1, W2, out);
    sort_kernel<<<NCTA, 32>>>(graph);
    for (int t = 0; t < TSTEPS - 1; ++t)
        for (int st = 0; st < 4; ++st)
            edge_kernel<<<NCTA, NTHR, SMEM_TOTAL>>>(b1, b2, W3, b3, ts, t, st, out);
}

// round 11
// speedup vs baseline: 1.0011x; 1.0004x over previous
#include <cuda_runtime.h>
#include <cuda_bf16.h>
#include <cstdint>

#define BATCH 64
#define NNODE 50
#define FDIM 64
#define HDIM 128
#define EDGES 2450
#define TSTEPS 40
#define CHUNK 128
#define MAXROWS 896
#define NQ 4
#define NCTA (BATCH*NQ)      // 256
#define NTHR 128

// ---- smem byte offsets ----
#define OFF_W    0           // 4 tiles x 16KB (W1 h0,h1, W2 h0,h1 of current k)
#define OFF_PRE0 65536       // 16384
#define OFF_PRE1 81920       // 16384
#define OFF_Y    98304       // 6400
#define OFF_B1   104704
#define OFF_B2   105728
#define OFF_B3   106752
#define OFF_AGG  107008      // S tile (16x136 bf16) during chunks; agg fp32 after
#define OFF_RT   113664      // 512
#define SMEM_TOTAL 114176

#define SWZ(o) ((o) ^ (((o) >> 3) & 0x70))
#define SSTRIDE 136

// ---------------- device scratch ----------------
__device__ float          g_y[BATCH*NNODE*FDIM];
__device__ float          g_ksum[BATCH*NNODE*FDIM];
__device__ __nv_bfloat16  g_ybf[BATCH*NNODE*FDIM];
__device__ __nv_bfloat16  g_Wt[8*8192];
__device__ int            g_rows[NCTA*MAXROWS];
__device__ int            g_nrows[NCTA];

// ---------------- helpers ----------------
__device__ __forceinline__ void mma16816(float* c, const uint32_t* a, const uint32_t* b) {
    asm volatile(
        "mma.sync.aligned.m16n8k16.row.col.f32.bf16.bf16.f32 "
        "{%0,%1,%2,%3}, {%4,%5,%6,%7}, {%8,%9}, {%0,%1,%2,%3};\n"
        : "+f"(c[0]), "+f"(c[1]), "+f"(c[2]), "+f"(c[3])
        : "r"(a[0]), "r"(a[1]), "r"(a[2]), "r"(a[3]), "r"(b[0]), "r"(b[1]));
}
__device__ __forceinline__ void ldsm4(uint32_t* r, uint32_t addr) {
    asm volatile("ldmatrix.sync.aligned.m8n8.x4.shared.b16 {%0,%1,%2,%3}, [%4];"
                 : "=r"(r[0]), "=r"(r[1]), "=r"(r[2]), "=r"(r[3]) : "r"(addr));
}
__device__ __forceinline__ void ldsm4t(uint32_t* r, uint32_t addr) {
    asm volatile("ldmatrix.sync.aligned.m8n8.x4.trans.shared.b16 {%0,%1,%2,%3}, [%4];"
                 : "=r"(r[0]), "=r"(r[1]), "=r"(r[2]), "=r"(r[3]) : "r"(addr));
}
__device__ __forceinline__ uint32_t smem_u32(const void* p) {
    uint32_t a;
    asm("{ .reg .u64 t; cvta.to.shared.u64 t, %1; cvt.u32.u64 %0, t; }" : "=r"(a) : "l"(p));
    return a;
}
__device__ __forceinline__ uint32_t packbf(float x, float y) {
    __nv_bfloat162 t = __floats2bfloat162_rn(x, y);
    return *reinterpret_cast<uint32_t*>(&t);
}

// ---------------- prep ----------------
__global__ void prep_kernel(const float* __restrict__ fp,
                            const float* __restrict__ W1,
                            const float* __restrict__ W2,
                            float* __restrict__ out) {
    int gsz = gridDim.x * blockDim.x;
    int g0  = blockIdx.x * blockDim.x + threadIdx.x;
    for (int i = g0; i < 4*HDIM*HDIM; i += gsz) {
        int s = i >> 14, rem = i & 16383;
        int n = rem >> 7, k = rem & 127;
        float v = (s < 2) ? W1[s*16384 + k*HDIM + n] : W2[(s-2)*16384 + k*HDIM + n];
        int tile = s*2 + (k >> 6);
        uint32_t boff = (uint32_t)(n*128 + (k & 63)*2);
        g_Wt[tile*8192 + (SWZ(boff) >> 1)] = __float2bfloat16(v);
    }
    for (int i = g0; i < BATCH*NNODE*FDIM; i += gsz) {
        float v = fp[i];
        g_y[i]   = v;
        g_ybf[i] = __float2bfloat16(v);
        out[(i >> 6)*(TSTEPS*FDIM) + (i & 63)] = v;
    }
}

// ---------------- sort ----------------
__global__ void sort_kernel(const int* __restrict__ graph) {
    const int cta = blockIdx.x;
    const int b = cta >> 2, q = cta & 3;
    const int rstart = (q < 2) ? q*13 : 26 + (q-2)*12;
    const int rcnt   = (q < 2) ? 13 : 12;
    const int ebase  = rstart * 49;
    const int ecnt   = rcnt * 49;
    const int lane = threadIdx.x;
    int* rows = g_rows + cta * MAXROWS;
    int row = 0;
#pragma unroll
    for (int k = 0; k < 2; ++k) {
        for (int i0 = 0; i0 < ecnt; i0 += 32) {
            int i = i0 + lane;
            bool m = false; int meta = 0;
            if (i < ecnt) {
                int e = ebase + i;
                int kk = graph[b*EDGES + e];
                int r = e / 49, j = e - r*49;
                int s = j + (j >= r);
                meta = (kk << 16) | (r << 8) | s;
                m = (kk == k);
            }
            unsigned mask = __ballot_sync(0xffffffffu, m);
            if (m) rows[row + __popc(mask & ((1u << lane) - 1u))] = meta;
            row += __popc(mask);
        }
        int pad = (128 - (row & 127)) & 127;
        for (int i = lane; i < pad; i += 32) rows[row + i] = -1;
        row += pad;
    }
    if (lane == 0) g_nrows[cta] = row;
}

// ---------------- fused edge+node kernel: 4 warps, 64x64 tiles ----------------
__global__ void __launch_bounds__(NTHR, 2)
edge_kernel(const float* __restrict__ b1f, const float* __restrict__ b2f,
            const float* __restrict__ W3,  const float* __restrict__ b3f,
            const float* __restrict__ ts,  int t, int stage,
            float* __restrict__ out) {
    extern __shared__ char smb[];
    const int tid  = threadIdx.x;
    const int lane = tid & 31, wid = tid >> 5;     // wid 0..3
    const int cta  = blockIdx.x;
    const int b = cta >> 2, q = cta & 3;
    const int rstart = (q < 2) ? q*13 : 26 + (q-2)*12;
    const int nloc   = (q < 2) ? 13 : 12;

    {
        const uint4* src = reinterpret_cast<const uint4*>(g_ybf + b*NNODE*FDIM);
        uint4* dst = reinterpret_cast<uint4*>(smb + OFF_Y);
        for (int i = tid; i < 6400/16; i += NTHR) dst[i] = src[i];
    }
    for (int i = tid; i < 2*HDIM; i += NTHR) {
        ((float*)(smb + OFF_B1))[i] = b1f[i];
        ((float*)(smb + OFF_B2))[i] = b2f[i];
    }
    if (tid < 64) ((float*)(smb + OFF_B3))[tid] = b3f[tid];

    const float* sB1 = (float*)(smb + OFF_B1);
    const float* sB2 = (float*)(smb + OFF_B2);
    int* sRt = (int*)(smb + OFF_RT);
    __nv_bfloat16* sS = (__nv_bfloat16*)(smb + OFF_AGG);

    const int nch = g_nrows[cta] >> 7;
    const int* __restrict__ rows = g_rows + cta * MAXROWS;

    // warp tiling: 2x2 grid of 64x64 tiles
    const int wm = (wid & 1) * 64;
    const int wn = (wid >> 1) * 64;
    const int g = lane >> 2, tig = lane & 3;
    const int li = lane & 7, lm = lane >> 3;
    const int aRow = (lm & 1)*8 + li;
    const int aK16 = (lm >> 1) * 16;
    const int bRow = (lm >> 1)*8 + li;
    const int bK16 = (lm & 1) * 16;

    const uint32_t uPre0 = smem_u32(smb + OFF_PRE0);
    const uint32_t uPre1 = smem_u32(smb + OFF_PRE1);
    const uint32_t uW    = smem_u32(smb + OFF_W);
    const uint32_t uS    = smem_u32(smb + OFF_AGG);

    // agg-GEMM: warp owns m cols wid*32..wid*32+31
    const uint32_t aggBase = (wid >> 1) ? uPre1 : uPre0;
    const uint32_t aggRowL = (uint32_t)((lm & 1)*8 + li);
    const uint32_t aggColL = (uint32_t)(((wid & 1)*32 + (lm >> 1)*8) * 2);
    const uint32_t sA0 = uS + (uint32_t)(g*(SSTRIDE*2) + 2*tig*2);

    float Ca[4][4];
#pragma unroll
    for (int i = 0; i < 4; ++i) { Ca[i][0]=0.f; Ca[i][1]=0.f; Ca[i][2]=0.f; Ca[i][3]=0.f; }

    int curk = -1;

    for (int ch = 0; ch < nch; ++ch) {
        const int* crow = rows + ch*CHUNK;
        const int k = (crow[0] >> 16);

        if (k != curk) {
            curk = k;
            const uint4* s1 = reinterpret_cast<const uint4*>(g_Wt + (k*2)*8192);
            const uint4* s2 = reinterpret_cast<const uint4*>(g_Wt + ((2 + k)*2)*8192);
            uint4* d1 = reinterpret_cast<uint4*>(smb + OFF_W);
            uint4* d2 = reinterpret_cast<uint4*>(smb + OFF_W + 32768);
            for (int i = tid; i < 2048; i += NTHR) { d1[i] = s1[i]; d2[i] = s2[i]; }
        }

        // zero S tile
        {
            uint32_t* s32 = (uint32_t*)sS;
            for (int i = tid; i < 16*SSTRIDE/2; i += NTHR) s32[i] = 0;
        }
        // gather: one row per thread (both halves) + receiver meta
        {
            int row = tid;
            int v = crow[row];
            sRt[row] = (v < 0) ? -1 : ((v >> 8) & 255);
            if (v >= 0) {
                int nsend = v & 255, nrecv = (v >> 8) & 255;
                const uint4* s0 = (const uint4*)(smb + OFF_Y + nsend*FDIM*2);
                const uint4* s1 = (const uint4*)(smb + OFF_Y + nrecv*FDIM*2);
#pragma unroll
                for (int qq = 0; qq < 8; ++qq) {
                    uint32_t o = SWZ((uint32_t)(row*128 + qq*16));
                    *(uint4*)(smb + OFF_PRE0 + o) = s0[qq];
                    *(uint4*)(smb + OFF_PRE1 + o) = s1[qq];
                }
            } else {
                uint4 z = make_uint4(0,0,0,0);
#pragma unroll
                for (int qq = 0; qq < 8; ++qq) {
                    uint32_t o = SWZ((uint32_t)(row*128 + qq*16));
                    *(uint4*)(smb + OFF_PRE0 + o) = z;
                    *(uint4*)(smb + OFF_PRE1 + o) = z;
                }
            }
        }
        __syncthreads();

        // scatter S ones
        if (tid < 128) {
            int rr = sRt[tid];
            if (rr >= 0) sS[(rr - rstart)*SSTRIDE + tid] = __float2bfloat16(1.0f);
        }

        float C[32][4];

        // ==== GEMM1: C[64x64] = pre @ W1[k]^T ====
#pragma unroll
        for (int i = 0; i < 32; ++i) { C[i][0]=0.f; C[i][1]=0.f; C[i][2]=0.f; C[i][3]=0.f; }
#pragma unroll
        for (int kb = 0; kb < 8; ++kb) {
            const int half = kb >> 2;
            const uint32_t kgrp = (uint32_t)((kb & 3) * 32);
            const uint32_t aBase = half ? uPre1 : uPre0;
            uint32_t a[4][4];
#pragma unroll
            for (int mt = 0; mt < 4; ++mt) {
                uint32_t o = (uint32_t)((wm + mt*16 + aRow)*128) + kgrp + aK16;
                ldsm4(a[mt], aBase + SWZ(o));
            }
            uint32_t bf[4][4];
#pragma unroll
            for (int nt2 = 0; nt2 < 4; ++nt2) {
                uint32_t o = (uint32_t)((wn + nt2*16 + bRow)*128) + kgrp + bK16;
                ldsm4(bf[nt2], uW + half*16384u + SWZ(o));
            }
#pragma unroll
            for (int mt = 0; mt < 4; ++mt)
#pragma unroll
                for (int nt = 0; nt < 8; ++nt)
                    mma16816(C[mt*8 + nt], a[mt], &bf[nt >> 1][(nt & 1)*2]);
        }
        __syncthreads();

        // epilogue1: h = relu(C + b1[k]) -> PRE halves
        {
            const int hh = wn >> 6;
            char* tb = smb + (hh ? OFF_PRE1 : OFF_PRE0);
#pragma unroll
            for (int mt = 0; mt < 4; ++mt)
#pragma unroll
                for (int nt = 0; nt < 8; ++nt) {
                    int r0 = wm + mt*16 + g, r1 = r0 + 8;
                    int c = wn + nt*8 + 2*tig;
                    float b0v = sB1[k*HDIM + c], b1v = sB1[k*HDIM + c + 1];
                    float* x = C[mt*8 + nt];
                    uint32_t cb = (uint32_t)((c & 63)*2);
                    *(uint32_t*)(tb + SWZ((uint32_t)(r0*128) + cb)) =
                        packbf(fmaxf(x[0]+b0v,0.f), fmaxf(x[1]+b1v,0.f));
                    *(uint32_t*)(tb + SWZ((uint32_t)(r1*128) + cb)) =
                        packbf(fmaxf(x[2]+b0v,0.f), fmaxf(x[3]+b1v,0.f));
                }
        }
        __syncthreads();

        // ==== GEMM2: C = h @ W2[k]^T ====
#pragma unroll
        for (int i = 0; i < 32; ++i) { C[i][0]=0.f; C[i][1]=0.f; C[i][2]=0.f; C[i][3]=0.f; }
#pragma unroll
        for (int kb = 0; kb < 8; ++kb) {
            const int half = kb >> 2;
            const uint32_t kgrp = (uint32_t)((kb & 3) * 32);
            const uint32_t aBase = half ? uPre1 : uPre0;
            uint32_t a[4][4];
#pragma unroll
            for (int mt = 0; mt < 4; ++mt) {
                uint32_t o = (uint32_t)((wm + mt*16 + aRow)*128) + kgrp + aK16;
                ldsm4(a[mt], aBase + SWZ(o));
            }
            uint32_t bf[4][4];
#pragma unroll
            for (int nt2 = 0; nt2 < 4; ++nt2) {
                uint32_t o = (uint32_t)((wn + nt2*16 + bRow)*128) + kgrp + bK16;
                ldsm4(bf[nt2], uW + 32768u + half*16384u + SWZ(o));
            }
#pragma unroll
            for (int mt = 0; mt < 4; ++mt)
#pragma unroll
                for (int nt = 0; nt < 8; ++nt)
                    mma16816(C[mt*8 + nt], a[mt], &bf[nt >> 1][(nt & 1)*2]);
        }
        __syncthreads();

        // epilogue2: m = relu(C + b2[k]) -> PRE halves
        {
            const int hh = wn >> 6;
            char* tb = smb + (hh ? OFF_PRE1 : OFF_PRE0);
#pragma unroll
            for (int mt = 0; mt < 4; ++mt)
#pragma unroll
                for (int nt = 0; nt < 8; ++nt) {
                    int r0 = wm + mt*16 + g, r1 = r0 + 8;
                    int c = wn + nt*8 + 2*tig;
                    float b0v = sB2[k*HDIM + c], b1v = sB2[k*HDIM + c + 1];
                    float* x = C[mt*8 + nt];
                    uint32_t cb = (uint32_t)((c & 63)*2);
                    *(uint32_t*)(tb + SWZ((uint32_t)(r0*128) + cb)) =
                        packbf(fmaxf(x[0]+b0v,0.f), fmaxf(x[1]+b1v,0.f));
                    *(uint32_t*)(tb + SWZ((uint32_t)(r1*128) + cb)) =
                        packbf(fmaxf(x[2]+b0v,0.f), fmaxf(x[3]+b1v,0.f));
                }
        }
        __syncthreads();

        // ==== agg GEMM: Ca += S @ m (warp owns m cols wid*32..+31) ====
#pragma unroll
        for (int kb = 0; kb < 8; ++kb) {
            uint32_t a[4];
            uint32_t aoff = sA0 + (uint32_t)(kb*32);
            asm volatile("ld.shared.b32 %0, [%1];" : "=r"(a[0]) : "r"(aoff));
            asm volatile("ld.shared.b32 %0, [%1];" : "=r"(a[1]) : "r"(aoff + 8*(SSTRIDE*2)));
            asm volatile("ld.shared.b32 %0, [%1];" : "=r"(a[2]) : "r"(aoff + 16));
            asm volatile("ld.shared.b32 %0, [%1];" : "=r"(a[3]) : "r"(aoff + 8*(SSTRIDE*2) + 16));
#pragma unroll
            for (int c2 = 0; c2 < 2; ++c2) {
                uint32_t bf[4];
                uint32_t o = (uint32_t)((kb*16 + aggRowL)*128) + aggColL + (uint32_t)(c2*32);
                ldsm4t(bf, aggBase + SWZ(o));
                mma16816(Ca[c2*2],     a, bf);
                mma16816(Ca[c2*2 + 1], a, bf + 2);
            }
        }
        __syncthreads();
    }

    // write register agg to smem (S region reused as fp32 agg [nloc][128])
    {
        float* agg = (float*)(smb + OFF_AGG);
#pragma unroll
        for (int i = 0; i < 4; ++i) {
            int c = wid*32 + i*8 + 2*tig;
            if (g < nloc) {
                agg[g*HDIM + c]     = Ca[i][0];
                agg[g*HDIM + c + 1] = Ca[i][1];
            }
            if (g + 8 < nloc) {
                agg[(g+8)*HDIM + c]     = Ca[i][2];
                agg[(g+8)*HDIM + c + 1] = Ca[i][3];
            }
        }
    }
    __syncthreads();

    // ---- node phase ----
    {
        float* w3 = (float*)(smb + OFF_PRE0);
        for (int i = tid; i < HDIM*FDIM; i += NTHR) w3[i] = W3[i];
    }
    __syncthreads();
    {
        const float dt = ts[t+1] - ts[t];
        const float inv_n = 1.0f / (float)NNODE;
        const float* agg = (float*)(smb + OFF_AGG);
        const float* w3  = (float*)(smb + OFF_PRE0);
        const float* sb3 = (float*)(smb + OFF_B3);
        for (int idx = tid; idx < nloc*FDIM; idx += NTHR) {
            int n = idx >> 6, j = idx & 63;
            const float* ar = agg + n*HDIM;
            float acc = 0.f;
#pragma unroll 8
            for (int h = 0; h < HDIM; ++h)
                acc = fmaf(ar[h], w3[h*FDIM + j], acc);
            float kv = tanhf(acc * inv_n + sb3[j]);
            int gi = (b*NNODE + rstart + n)*FDIM + j;
            float yv = g_y[gi];
            float yin;
            if (stage == 0)      { g_ksum[gi] = kv;        yin = yv + 0.5f*dt*kv; }
            else if (stage == 1) { g_ksum[gi] += 2.f*kv;   yin = yv + 0.5f*dt*kv; }
            else if (stage == 2) { g_ksum[gi] += 2.f*kv;   yin = yv + dt*kv; }
            else {
                float yn = yv + dt*(1.f/6.f)*(g_ksum[gi] + kv);
                g_y[gi] = yn;
                out[(b*NNODE + rstart + n)*(TSTEPS*FDIM) + (t+1)*FDIM + j] = yn;
                yin = yn;
            }
            g_ybf[gi] = __float2bfloat16(yin);
        }
    }
}

// ---------------- launcher ----------------
extern "C" void kernel_launch(void* const* d_in, const int* in_sizes, int n_in,
                              void* d_out, int out_size) {
    const float* fp    = (const float*)d_in[0];
    const float* ts    = (const float*)d_in[1];
    const int*   graph = (const int*)d_in[2];
    const float* W1    = (const float*)d_in[3];
    const float* b1    = (const float*)d_in[4];
    const float* W2    = (const float*)d_in[5];
    const float* b2    = (const float*)d_in[6];
    const float* W3    = (const float*)d_in[7];
    const float* b3    = (const float*)d_in[8];
    float* out = (float*)d_out;

    cudaFuncSetAttribute(edge_kernel, cudaFuncAttributeMaxDynamicSharedMemorySize, SMEM_TOTAL);

    prep_kernel<<<256, 256>>>(fp, W1, W2, out);
    sort_kernel<<<NCTA, 32>>>(graph);
    for (int t = 0; t < TSTEPS - 1; ++t)
        for (int st = 0; st < 4; ++st)
            edge_kernel<<<NCTA, NTHR, SMEM_TOTAL>>>(b1, b2, W3, b3, ts, t, st, out);
}

// round 12
// speedup vs baseline: 1.0090x; 1.0079x over previous
#include <cuda_runtime.h>
#include <cuda_bf16.h>
#include <cstdint>

#define BATCH 64
#define NNODE 50
#define FDIM 64
#define HDIM 128
#define EDGES 2450
#define TSTEPS 40
#define CHUNK 128
#define MAXROWS 1408
#define NCTA 128             // 64 batches x 2 halves
#define NTHR 256
#define NLOC 25

// ---- smem byte offsets ----
#define OFF_W   0            // 8 tiles x 16KB = 131072 (W1k0,W1k1,W2k0,W2k1 x 2 halves)
#define OFF_T0  131072       // tile buffer 0 (2 x 16KB halves)
#define OFF_T1  163840       // tile buffer 1
#define OFF_Y   196608       // 6400
#define OFF_B1  203008       // 1024
#define OFF_B2  204032       // 1024
#define OFF_B3  205056       // 256
#define OFF_S   205312       // 2 x 8704 S tiles; reused as agg fp32 [25][128] after chunks
#define SMEM_TOTAL 223232

#define SWZ(o) ((o) ^ (((o) >> 3) & 0x70))
#define SSTRIDE 136
#define SBYTES 8704          // 32 rows x 136 bf16

// ---------------- device scratch ----------------
__device__ float          g_y[BATCH*NNODE*FDIM];
__device__ float          g_ksum[BATCH*NNODE*FDIM];
__device__ __nv_bfloat16  g_ybf[BATCH*NNODE*FDIM];
__device__ __nv_bfloat16  g_Wt[8*8192];
__device__ int            g_rows[NCTA*MAXROWS];
__device__ int            g_nrows[NCTA];

// ---------------- helpers ----------------
__device__ __forceinline__ void mma16816(float* c, const uint32_t* a, const uint32_t* b) {
    asm volatile(
        "mma.sync.aligned.m16n8k16.row.col.f32.bf16.bf16.f32 "
        "{%0,%1,%2,%3}, {%4,%5,%6,%7}, {%8,%9}, {%0,%1,%2,%3};\n"
        : "+f"(c[0]), "+f"(c[1]), "+f"(c[2]), "+f"(c[3])
        : "r"(a[0]), "r"(a[1]), "r"(a[2]), "r"(a[3]), "r"(b[0]), "r"(b[1]));
}
__device__ __forceinline__ void ldsm4(uint32_t* r, uint32_t addr) {
    asm volatile("ldmatrix.sync.aligned.m8n8.x4.shared.b16 {%0,%1,%2,%3}, [%4];"
                 : "=r"(r[0]), "=r"(r[1]), "=r"(r[2]), "=r"(r[3]) : "r"(addr));
}
__device__ __forceinline__ void ldsm4t(uint32_t* r, uint32_t addr) {
    asm volatile("ldmatrix.sync.aligned.m8n8.x4.trans.shared.b16 {%0,%1,%2,%3}, [%4];"
                 : "=r"(r[0]), "=r"(r[1]), "=r"(r[2]), "=r"(r[3]) : "r"(addr));
}
__device__ __forceinline__ uint32_t smem_u32(const void* p) {
    uint32_t a;
    asm("{ .reg .u64 t; cvta.to.shared.u64 t, %1; cvt.u32.u64 %0, t; }" : "=r"(a) : "l"(p));
    return a;
}
__device__ __forceinline__ uint32_t packbf(float x, float y) {
    __nv_bfloat162 t = __floats2bfloat162_rn(x, y);
    return *reinterpret_cast<uint32_t*>(&t);
}

// ---------------- prep ----------------
__global__ void prep_kernel(const float* __restrict__ fp,
                            const float* __restrict__ W1,
                            const float* __restrict__ W2,
                            float* __restrict__ out) {
    int gsz = gridDim.x * blockDim.x;
    int g0  = blockIdx.x * blockDim.x + threadIdx.x;
    for (int i = g0; i < 4*HDIM*HDIM; i += gsz) {
        int s = i >> 14, rem = i & 16383;
        int n = rem >> 7, k = rem & 127;
        float v = (s < 2) ? W1[s*16384 + k*HDIM + n] : W2[(s-2)*16384 + k*HDIM + n];
        int tile = s*2 + (k >> 6);
        uint32_t boff = (uint32_t)(n*128 + (k & 63)*2);
        g_Wt[tile*8192 + (SWZ(boff) >> 1)] = __float2bfloat16(v);
    }
    for (int i = g0; i < BATCH*NNODE*FDIM; i += gsz) {
        float v = fp[i];
        g_y[i]   = v;
        g_ybf[i] = __float2bfloat16(v);
        out[(i >> 6)*(TSTEPS*FDIM) + (i & 63)] = v;
    }
}

// ---------------- sort: per-half stable partition by type ----------------
__global__ void sort_kernel(const int* __restrict__ graph) {
    const int cta = blockIdx.x;            // b*2 + hb
    const int b = cta >> 1, hb = cta & 1;
    const int ebase = hb * NLOC * 49;      // 1225 edges per half
    const int ecnt  = NLOC * 49;
    const int lane = threadIdx.x;
    int* rows = g_rows + cta * MAXROWS;
    int row = 0;
#pragma unroll
    for (int k = 0; k < 2; ++k) {
        for (int i0 = 0; i0 < ecnt; i0 += 32) {
            int i = i0 + lane;
            bool m = false; int meta = 0;
            if (i < ecnt) {
                int e = ebase + i;
                int kk = graph[b*EDGES + e];
                int r = e / 49, j = e - r*49;
                int s = j + (j >= r);
                meta = (kk << 16) | (r << 8) | s;
                m = (kk == k);
            }
            unsigned mask = __ballot_sync(0xffffffffu, m);
            if (m) rows[row + __popc(mask & ((1u << lane) - 1u))] = meta;
            row += __popc(mask);
        }
        int pad = (128 - (row & 127)) & 127;
        for (int i = lane; i < pad; i += 32) rows[row + i] = -1;
        row += pad;
    }
    if (lane == 0) g_nrows[cta] = row;
}

// ---------------- fused edge+node kernel: 1 CTA/SM, 255 regs, 3 syncs/chunk ----------------
__global__ void __launch_bounds__(NTHR, 1)
edge_kernel(const float* __restrict__ b1f, const float* __restrict__ b2f,
            const float* __restrict__ W3,  const float* __restrict__ b3f,
            const float* __restrict__ ts,  int t, int stage,
            float* __restrict__ out) {
    extern __shared__ char smb[];
    const int tid  = threadIdx.x;
    const int lane = tid & 31, wid = tid >> 5;   // 8 warps
    const int cta  = blockIdx.x;
    const int b = cta >> 1, hb = cta & 1;
    const int rstart = hb * NLOC;

    // ---- load all weights (128KB), y, biases; zero S[0] ----
    {
        const uint4* src = reinterpret_cast<const uint4*>(g_Wt);
        uint4* dst = reinterpret_cast<uint4*>(smb + OFF_W);
        for (int i = tid; i < 131072/16; i += NTHR) dst[i] = src[i];
    }
    {
        const uint4* src = reinterpret_cast<const uint4*>(g_ybf + b*NNODE*FDIM);
        uint4* dst = reinterpret_cast<uint4*>(smb + OFF_Y);
        for (int i = tid; i < 6400/16; i += NTHR) dst[i] = src[i];
    }
    ((float*)(smb + OFF_B1))[tid] = b1f[tid];
    ((float*)(smb + OFF_B2))[tid] = b2f[tid];
    if (tid < 64) ((float*)(smb + OFF_B3))[tid] = b3f[tid];
    {
        uint32_t* s0 = (uint32_t*)(smb + OFF_S);
        for (int i = tid; i < SBYTES/4; i += NTHR) s0[i] = 0;
    }

    const float* sB1 = (float*)(smb + OFF_B1);
    const float* sB2 = (float*)(smb + OFF_B2);

    const int nch = g_nrows[cta] >> 7;
    const int* __restrict__ rows = g_rows + cta * MAXROWS;

    // warp tiling: 2M x 4N of 64x32 tiles
    const int wm = (wid & 1) * 64;
    const int wn = (wid >> 1) * 32;
    const int g = lane >> 2, tig = lane & 3;
    const int li = lane & 7, lm = lane >> 3;
    const int aRow = (lm & 1)*8 + li;
    const int aK16 = (lm >> 1) * 16;
    const int bRow = (lm >> 1)*8 + li;
    const int bK16 = (lm & 1) * 16;

    const uint32_t uT0 = smem_u32(smb + OFF_T0);
    const uint32_t uT1 = smem_u32(smb + OFF_T1);
    const uint32_t uW  = smem_u32(smb + OFF_W);
    const uint32_t uS  = smem_u32(smb + OFF_S);

    // agg-GEMM invariants: warp owns m cols wid*16..wid*16+15; S rows 0..31
    const uint32_t aggHalf = (wid >= 4) ? 16384u : 0u;
    const uint32_t aggRowL = (uint32_t)((lm & 1)*8 + li);
    const uint32_t aggColL = (uint32_t)(((wid & 3)*16 + (lm >> 1)*8) * 2);
    const uint32_t sAbase = (uint32_t)(g*(SSTRIDE*2) + 2*tig*2);

    float Ca[2][2][4];
#pragma unroll
    for (int i = 0; i < 2; ++i)
#pragma unroll
        for (int j = 0; j < 2; ++j) { Ca[i][j][0]=0.f; Ca[i][j][1]=0.f; Ca[i][j][2]=0.f; Ca[i][j][3]=0.f; }

    __syncthreads();

    // ---- prologue: gather chunk 0 into T0, scatter S[0] ----
    {
        int row = tid >> 1, hlf = tid & 1;
        int v = rows[row];
        char* tb = smb + OFF_T0 + hlf*16384;
        if (v >= 0) {
            int node = hlf ? ((v >> 8) & 255) : (v & 255);
            const uint4* src = (const uint4*)(smb + OFF_Y + node*FDIM*2);
#pragma unroll
            for (int qq = 0; qq < 8; ++qq)
                *(uint4*)(tb + SWZ((uint32_t)(row*128 + qq*16))) = src[qq];
            if (hlf == 0) {
                int rr = ((v >> 8) & 255) - rstart;
                *(__nv_bfloat16*)(smb + OFF_S + rr*(SSTRIDE*2) + row*2) = __float2bfloat16(1.0f);
            }
        } else {
            uint4 z = make_uint4(0,0,0,0);
#pragma unroll
            for (int qq = 0; qq < 8; ++qq)
                *(uint4*)(tb + SWZ((uint32_t)(row*128 + qq*16))) = z;
        }
    }
    __syncthreads();

    for (int ch = 0; ch < nch; ++ch) {
        const int p = ch & 1;
        const uint32_t uP = p ? uT1 : uT0;
        const uint32_t uH = p ? uT0 : uT1;
        const int tHoff = p ? OFF_T0 : OFF_T1;
        const int tPoff = p ? OFF_T1 : OFF_T0;
        const int k = rows[ch*CHUNK] >> 16;
        const uint32_t w1base = uW + (uint32_t)(k*32768);
        const uint32_t w2base = uW + 65536u + (uint32_t)(k*32768);

        float C[16][4];

        // ==== interval 1: GEMM1 (A from P, B=W1[k]) + epi1 -> H ; zero S[1-p] ====
        if (ch + 1 < nch) {
            uint32_t* sz = (uint32_t*)(smb + OFF_S + (1-p)*SBYTES);
            for (int i = tid; i < SBYTES/4; i += NTHR) sz[i] = 0;
        }
#pragma unroll
        for (int i = 0; i < 16; ++i) { C[i][0]=0.f; C[i][1]=0.f; C[i][2]=0.f; C[i][3]=0.f; }
#pragma unroll
        for (int kb = 0; kb < 8; ++kb) {
            const uint32_t half16 = (uint32_t)((kb >> 2) * 16384);
            const uint32_t kgrp = (uint32_t)((kb & 3) * 32);
            uint32_t a[4][4];
#pragma unroll
            for (int mt = 0; mt < 4; ++mt) {
                uint32_t o = (uint32_t)((wm + mt*16 + aRow)*128) + kgrp + aK16;
                ldsm4(a[mt], uP + half16 + SWZ(o));
            }
            uint32_t bf[2][4];
#pragma unroll
            for (int nt2 = 0; nt2 < 2; ++nt2) {
                uint32_t o = (uint32_t)((wn + nt2*16 + bRow)*128) + kgrp + bK16;
                ldsm4(bf[nt2], w1base + half16 + SWZ(o));
            }
#pragma unroll
            for (int mt = 0; mt < 4; ++mt)
#pragma unroll
                for (int nt = 0; nt < 4; ++nt)
                    mma16816(C[mt*4 + nt], a[mt], &bf[nt >> 1][(nt & 1)*2]);
        }
        // epi1: h = relu(C + b1[k]) -> H (own warp's cols; no barrier needed first)
        {
            char* tb = smb + tHoff + ((wn >> 6) ? 16384 : 0);
#pragma unroll
            for (int mt = 0; mt < 4; ++mt)
#pragma unroll
                for (int nt = 0; nt < 4; ++nt) {
                    int r0 = wm + mt*16 + g, r1 = r0 + 8;
                    int c = wn + nt*8 + 2*tig;
                    float b0v = sB1[k*HDIM + c], b1v = sB1[k*HDIM + c + 1];
                    float* x = C[mt*4 + nt];
                    uint32_t cb = (uint32_t)((c & 63)*2);
                    *(uint32_t*)(tb + SWZ((uint32_t)(r0*128) + cb)) =
                        packbf(fmaxf(x[0]+b0v,0.f), fmaxf(x[1]+b1v,0.f));
                    *(uint32_t*)(tb + SWZ((uint32_t)(r1*128) + cb)) =
                        packbf(fmaxf(x[2]+b0v,0.f), fmaxf(x[3]+b1v,0.f));
                }
        }
        __syncthreads();

        // ==== interval 2: GEMM2 (A from H, B=W2[k]) + epi2 -> P ====
#pragma unroll
        for (int i = 0; i < 16; ++i) { C[i][0]=0.f; C[i][1]=0.f; C[i][2]=0.f; C[i][3]=0.f; }
#pragma unroll
        for (int kb = 0; kb < 8; ++kb) {
            const uint32_t half16 = (uint32_t)((kb >> 2) * 16384);
            const uint32_t kgrp = (uint32_t)((kb & 3) * 32);
            uint32_t a[4][4];
#pragma unroll
            for (int mt = 0; mt < 4; ++mt) {
                uint32_t o = (uint32_t)((wm + mt*16 + aRow)*128) + kgrp + aK16;
                ldsm4(a[mt], uH + half16 + SWZ(o));
            }
            uint32_t bf[2][4];
#pragma unroll
            for (int nt2 = 0; nt2 < 2; ++nt2) {
                uint32_t o = (uint32_t)((wn + nt2*16 + bRow)*128) + kgrp + bK16;
                ldsm4(bf[nt2], w2base + half16 + SWZ(o));
            }
#pragma unroll
            for (int mt = 0; mt < 4; ++mt)
#pragma unroll
                for (int nt = 0; nt < 4; ++nt)
                    mma16816(C[mt*4 + nt], a[mt], &bf[nt >> 1][(nt & 1)*2]);
        }
        // epi2: m = relu(C + b2[k]) -> P (pre reads finished at previous barrier)
        {
            char* tb = smb + tPoff + ((wn >> 6) ? 16384 : 0);
#pragma unroll
            for (int mt = 0; mt < 4; ++mt)
#pragma unroll
                for (int nt = 0; nt < 4; ++nt) {
                    int r0 = wm + mt*16 + g, r1 = r0 + 8;
                    int c = wn + nt*8 + 2*tig;
                    float b0v = sB2[k*HDIM + c], b1v = sB2[k*HDIM + c + 1];
                    float* x = C[mt*4 + nt];
                    uint32_t cb = (uint32_t)((c & 63)*2);
                    *(uint32_t*)(tb + SWZ((uint32_t)(r0*128) + cb)) =
                        packbf(fmaxf(x[0]+b0v,0.f), fmaxf(x[1]+b1v,0.f));
                    *(uint32_t*)(tb + SWZ((uint32_t)(r1*128) + cb)) =
                        packbf(fmaxf(x[2]+b0v,0.f), fmaxf(x[3]+b1v,0.f));
                }
        }
        __syncthreads();

        // ==== interval 3: agg MMA (S[p] @ m in P)  ||  gather ch+1 -> H + scatter S[1-p] ====
        {
            const uint32_t uSp = uS + (uint32_t)(p*SBYTES);
#pragma unroll
            for (int kb = 0; kb < 8; ++kb) {
                uint32_t a[2][4];
#pragma unroll
                for (int mg = 0; mg < 2; ++mg) {
                    uint32_t ao = uSp + sAbase + (uint32_t)(mg*16*(SSTRIDE*2) + kb*32);
                    asm volatile("ld.shared.b32 %0, [%1];" : "=r"(a[mg][0]) : "r"(ao));
                    asm volatile("ld.shared.b32 %0, [%1];" : "=r"(a[mg][1]) : "r"(ao + 8*(SSTRIDE*2)));
                    asm volatile("ld.shared.b32 %0, [%1];" : "=r"(a[mg][2]) : "r"(ao + 16));
                    asm volatile("ld.shared.b32 %0, [%1];" : "=r"(a[mg][3]) : "r"(ao + 8*(SSTRIDE*2) + 16));
                }
                uint32_t bf[4];
                uint32_t o = (uint32_t)((kb*16 + aggRowL)*128) + aggColL;
                ldsm4t(bf, uP + aggHalf + SWZ(o));
                mma16816(Ca[0][0], a[0], bf);
                mma16816(Ca[0][1], a[0], bf + 2);
                mma16816(Ca[1][0], a[1], bf);
                mma16816(Ca[1][1], a[1], bf + 2);
            }
        }
        if (ch + 1 < nch) {
            int row = tid >> 1, hlf = tid & 1;
            int v = rows[(ch+1)*CHUNK + row];
            char* tb = smb + tHoff + hlf*16384;
            if (v >= 0) {
                int node = hlf ? ((v >> 8) & 255) : (v & 255);
                const uint4* src = (const uint4*)(smb + OFF_Y + node*FDIM*2);
#pragma unroll
                for (int qq = 0; qq < 8; ++qq)
                    *(uint4*)(tb + SWZ((uint32_t)(row*128 + qq*16))) = src[qq];
                if (hlf == 0) {
                    int rr = ((v >> 8) & 255) - rstart;
                    *(__nv_bfloat16*)(smb + OFF_S + (1-p)*SBYTES + rr*(SSTRIDE*2) + row*2) =
                        __float2bfloat16(1.0f);
                }
            } else {
                uint4 z = make_uint4(0,0,0,0);
#pragma unroll
                for (int qq = 0; qq < 8; ++qq)
                    *(uint4*)(tb + SWZ((uint32_t)(row*128 + qq*16))) = z;
            }
        }
        __syncthreads();
    }

    // ---- write register agg to smem (S region reused as fp32 agg [25][128]) ----
    {
        float* agg = (float*)(smb + OFF_S);
#pragma unroll
        for (int mg = 0; mg < 2; ++mg)
#pragma unroll
            for (int n8 = 0; n8 < 2; ++n8) {
                int r0 = mg*16 + g;
                int c = wid*16 + n8*8 + 2*tig;
                float* x = Ca[mg][n8];
                if (r0 < NLOC) {
                    agg[r0*HDIM + c]     = x[0];
                    agg[r0*HDIM + c + 1] = x[1];
                }
                if (r0 + 8 < NLOC) {
                    agg[(r0+8)*HDIM + c]     = x[2];
                    agg[(r0+8)*HDIM + c + 1] = x[3];
                }
            }
    }
    __syncthreads();

    // ---- node phase: stage W3 into T0 (32KB fp32), GEMV + tanh + RK4 ----
    {
        float* w3 = (float*)(smb + OFF_T0);
        for (int i = tid; i < HDIM*FDIM; i += NTHR) w3[i] = W3[i];
    }
    __syncthreads();
    {
        const float dt = ts[t+1] - ts[t];
        const float inv_n = 1.0f / (float)NNODE;
        const float* agg = (float*)(smb + OFF_S);
        const float* w3  = (float*)(smb + OFF_T0);
        const float* sb3 = (float*)(smb + OFF_B3);
        for (int idx = tid; idx < NLOC*FDIM; idx += NTHR) {
            int n = idx >> 6, j = idx & 63;
            const float* ar = agg + n*HDIM;
            float acc = 0.f;
#pragma unroll 8
            for (int h = 0; h < HDIM; ++h)
                acc = fmaf(ar[h], w3[h*FDIM + j], acc);
            float kv = tanhf(acc * inv_n + sb3[j]);
            int gi = (b*NNODE + rstart + n)*FDIM + j;
            float yv = g_y[gi];
            float yin;
            if (stage == 0)      { g_ksum[gi] = kv;        yin = yv + 0.5f*dt*kv; }
            else if (stage == 1) { g_ksum[gi] += 2.f*kv;   yin = yv + 0.5f*dt*kv; }
            else if (stage == 2) { g_ksum[gi] += 2.f*kv;   yin = yv + dt*kv; }
            else {
                float yn = yv + dt*(1.f/6.f)*(g_ksum[gi] + kv);
                g_y[gi] = yn;
                out[(b*NNODE + rstart + n)*(TSTEPS*FDIM) + (t+1)*FDIM + j] = yn;
                yin = yn;
            }
            g_ybf[gi] = __float2bfloat16(yin);
        }
    }
}

// ---------------- launcher ----------------
extern "C" void kernel_launch(void* const* d_in, const int* in_sizes, int n_in,
                              void* d_out, int out_size) {
    const float* fp    = (const float*)d_in[0];
    const float* ts    = (const float*)d_in[1];
    const int*   graph = (const int*)d_in[2];
    const float* W1    = (const float*)d_in[3];
    const float* b1    = (const float*)d_in[4];
    const float* W2    = (const float*)d_in[5];
    const float* b2    = (const float*)d_in[6];
    const float* W3    = (const float*)d_in[7];
    const float* b3    = (const float*)d_in[8];
    float* out = (float*)d_out;

    cudaFuncSetAttribute(edge_kernel, cudaFuncAttributeMaxDynamicSharedMemorySize, SMEM_TOTAL);

    prep_kernel<<<256, 256>>>(fp, W1, W2, out);
    sort_kernel<<<NCTA, 32>>>(graph);
    for (int t = 0; t < TSTEPS - 1; ++t)
        for (int st = 0; st < 4; ++st)
            edge_kernel<<<NCTA, NTHR, SMEM_TOTAL>>>(b1, b2, W3, b3, ts, t, st, out);
}

// round 13
// speedup vs baseline: 1.0301x; 1.0209x over previous
#include <cuda_runtime.h>
#include <cuda_bf16.h>
#include <cstdint>

#define BATCH 64
#define NNODE 50
#define FDIM 64
#define HDIM 128
#define EDGES 2450
#define TSTEPS 40
#define CHUNK 128
#define MAXROWS 1408
#define NCTA 128             // 64 batches x 2 halves
#define NTHR 256
#define NLOC 25
#define NSTAGE ((TSTEPS-1)*4)

// ---- smem byte offsets ----
#define OFF_W   0            // 8 tiles x 16KB = 131072
#define OFF_T0  131072       // tile buffer 0 (2 x 16KB halves)
#define OFF_T1  163840       // tile buffer 1
#define OFF_Y   196608       // 6400
#define OFF_B1  203008       // 1024
#define OFF_B2  204032       // 1024
#define OFF_B3  205056       // 256
#define OFF_S   205312       // 2 x 8704 S tiles; reused as agg fp32 [25][128]
#define OFF_TS  222720       // 40 floats
#define SMEM_TOTAL 223232

#define SWZ(o) ((o) ^ (((o) >> 3) & 0x70))
#define SSTRIDE 136
#define SBYTES 8704

// ---------------- device scratch ----------------
__device__ float          g_y[BATCH*NNODE*FDIM];
__device__ float          g_ksum[BATCH*NNODE*FDIM];
__device__ __nv_bfloat16  g_ybf[BATCH*NNODE*FDIM];
__device__ __nv_bfloat16  g_Wt[8*8192];
__device__ int            g_rows[NCTA*MAXROWS];
__device__ int            g_nrows[NCTA];
__device__ int            g_bar[BATCH];

// ---------------- helpers ----------------
__device__ __forceinline__ void mma16816(float* c, const uint32_t* a, const uint32_t* b) {
    asm volatile(
        "mma.sync.aligned.m16n8k16.row.col.f32.bf16.bf16.f32 "
        "{%0,%1,%2,%3}, {%4,%5,%6,%7}, {%8,%9}, {%0,%1,%2,%3};\n"
        : "+f"(c[0]), "+f"(c[1]), "+f"(c[2]), "+f"(c[3])
        : "r"(a[0]), "r"(a[1]), "r"(a[2]), "r"(a[3]), "r"(b[0]), "r"(b[1]));
}
__device__ __forceinline__ void ldsm4(uint32_t* r, uint32_t addr) {
    asm volatile("ldmatrix.sync.aligned.m8n8.x4.shared.b16 {%0,%1,%2,%3}, [%4];"
                 : "=r"(r[0]), "=r"(r[1]), "=r"(r[2]), "=r"(r[3]) : "r"(addr));
}
__device__ __forceinline__ void ldsm4t(uint32_t* r, uint32_t addr) {
    asm volatile("ldmatrix.sync.aligned.m8n8.x4.trans.shared.b16 {%0,%1,%2,%3}, [%4];"
                 : "=r"(r[0]), "=r"(r[1]), "=r"(r[2]), "=r"(r[3]) : "r"(addr));
}
__device__ __forceinline__ uint32_t smem_u32(const void* p) {
    uint32_t a;
    asm("{ .reg .u64 t; cvta.to.shared.u64 t, %1; cvt.u32.u64 %0, t; }" : "=r"(a) : "l"(p));
    return a;
}
__device__ __forceinline__ uint32_t packbf(float x, float y) {
    __nv_bfloat162 t = __floats2bfloat162_rn(x, y);
    return *reinterpret_cast<uint32_t*>(&t);
}

// ---------------- prep ----------------
__global__ void prep_kernel(const float* __restrict__ fp,
                            const float* __restrict__ W1,
                            const float* __restrict__ W2,
                            float* __restrict__ out) {
    int gsz = gridDim.x * blockDim.x;
    int g0  = blockIdx.x * blockDim.x + threadIdx.x;
    for (int i = g0; i < 4*HDIM*HDIM; i += gsz) {
        int s = i >> 14, rem = i & 16383;
        int n = rem >> 7, k = rem & 127;
        float v = (s < 2) ? W1[s*16384 + k*HDIM + n] : W2[(s-2)*16384 + k*HDIM + n];
        int tile = s*2 + (k >> 6);
        uint32_t boff = (uint32_t)(n*128 + (k & 63)*2);
        g_Wt[tile*8192 + (SWZ(boff) >> 1)] = __float2bfloat16(v);
    }
    for (int i = g0; i < BATCH*NNODE*FDIM; i += gsz) {
        float v = fp[i];
        g_y[i]   = v;
        g_ybf[i] = __float2bfloat16(v);
        out[(i >> 6)*(TSTEPS*FDIM) + (i & 63)] = v;
    }
    for (int i = g0; i < BATCH; i += gsz) g_bar[i] = 0;
}

// ---------------- sort: per-half stable partition by type ----------------
__global__ void sort_kernel(const int* __restrict__ graph) {
    const int cta = blockIdx.x;            // b*2 + hb
    const int b = cta >> 1, hb = cta & 1;
    const int ebase = hb * NLOC * 49;
    const int ecnt  = NLOC * 49;
    const int lane = threadIdx.x;
    int* rows = g_rows + cta * MAXROWS;
    int row = 0;
#pragma unroll
    for (int k = 0; k < 2; ++k) {
        for (int i0 = 0; i0 < ecnt; i0 += 32) {
            int i = i0 + lane;
            bool m = false; int meta = 0;
            if (i < ecnt) {
                int e = ebase + i;
                int kk = graph[b*EDGES + e];
                int r = e / 49, j = e - r*49;
                int s = j + (j >= r);
                meta = (kk << 16) | (r << 8) | s;
                m = (kk == k);
            }
            unsigned mask = __ballot_sync(0xffffffffu, m);
            if (m) rows[row + __popc(mask & ((1u << lane) - 1u))] = meta;
            row += __popc(mask);
        }
        int pad = (128 - (row & 127)) & 127;
        for (int i = lane; i < pad; i += 32) rows[row + i] = -1;
        row += pad;
    }
    if (lane == 0) g_nrows[cta] = row;
}

// ---------------- persistent fused kernel: all 156 RK4 stages in one launch ----------------
__global__ void __launch_bounds__(NTHR, 1)
persist_kernel(const float* __restrict__ b1f, const float* __restrict__ b2f,
               const float* __restrict__ W3,  const float* __restrict__ b3f,
               const float* __restrict__ tsp, float* __restrict__ out) {
    extern __shared__ char smb[];
    const int tid  = threadIdx.x;
    const int lane = tid & 31, wid = tid >> 5;   // 8 warps
    const int cta  = blockIdx.x;
    const int b = cta >> 1, hb = cta & 1;
    const int rstart = hb * NLOC;
    int* const barp = &g_bar[b];

    // ---- one-time: all weights (128KB), biases, ts ----
    {
        const uint4* src = reinterpret_cast<const uint4*>(g_Wt);
        uint4* dst = reinterpret_cast<uint4*>(smb + OFF_W);
        for (int i = tid; i < 131072/16; i += NTHR) dst[i] = src[i];
    }
    ((float*)(smb + OFF_B1))[tid] = b1f[tid];
    ((float*)(smb + OFF_B2))[tid] = b2f[tid];
    if (tid < 64) ((float*)(smb + OFF_B3))[tid] = b3f[tid];
    if (tid < TSTEPS) ((float*)(smb + OFF_TS))[tid] = tsp[tid];

    const float* sB1 = (float*)(smb + OFF_B1);
    const float* sB2 = (float*)(smb + OFF_B2);
    const float* sTs = (float*)(smb + OFF_TS);

    const int nch = g_nrows[cta] >> 7;
    const int* __restrict__ rows = g_rows + cta * MAXROWS;

    // warp tiling: 2M x 4N of 64x32 tiles
    const int wm = (wid & 1) * 64;
    const int wn = (wid >> 1) * 32;
    const int g = lane >> 2, tig = lane & 3;
    const int li = lane & 7, lm = lane >> 3;
    const int aRow = (lm & 1)*8 + li;
    const int aK16 = (lm >> 1) * 16;
    const int bRow = (lm >> 1)*8 + li;
    const int bK16 = (lm & 1) * 16;

    const uint32_t uT0 = smem_u32(smb + OFF_T0);
    const uint32_t uT1 = smem_u32(smb + OFF_T1);
    const uint32_t uW  = smem_u32(smb + OFF_W);
    const uint32_t uS  = smem_u32(smb + OFF_S);

    const uint32_t aggHalf = (wid >= 4) ? 16384u : 0u;
    const uint32_t aggRowL = (uint32_t)((lm & 1)*8 + li);
    const uint32_t aggColL = (uint32_t)(((wid & 3)*16 + (lm >> 1)*8) * 2);
    const uint32_t sAbase = (uint32_t)(g*(SSTRIDE*2) + 2*tig*2);

    for (int iter = 0; iter < NSTAGE; ++iter) {
        const int t = iter >> 2, stage = iter & 3;

        // ---- stage setup: reload y, zero S[0] ----
        {
            const uint4* src = reinterpret_cast<const uint4*>(g_ybf + b*NNODE*FDIM);
            uint4* dst = reinterpret_cast<uint4*>(smb + OFF_Y);
            for (int i = tid; i < 6400/16; i += NTHR) dst[i] = src[i];
        }
        {
            uint32_t* s0 = (uint32_t*)(smb + OFF_S);
            for (int i = tid; i < SBYTES/4; i += NTHR) s0[i] = 0;
        }
        float Ca[2][2][4];
#pragma unroll
        for (int i = 0; i < 2; ++i)
#pragma unroll
            for (int j = 0; j < 2; ++j) { Ca[i][j][0]=0.f; Ca[i][j][1]=0.f; Ca[i][j][2]=0.f; Ca[i][j][3]=0.f; }
        __syncthreads();

        // ---- prologue: gather chunk 0 into T0, scatter S[0] ----
        {
            int row = tid >> 1, hlf = tid & 1;
            int v = rows[row];
            char* tb = smb + OFF_T0 + hlf*16384;
            if (v >= 0) {
                int node = hlf ? ((v >> 8) & 255) : (v & 255);
                const uint4* src = (const uint4*)(smb + OFF_Y + node*FDIM*2);
#pragma unroll
                for (int qq = 0; qq < 8; ++qq)
                    *(uint4*)(tb + SWZ((uint32_t)(row*128 + qq*16))) = src[qq];
                if (hlf == 0) {
                    int rr = ((v >> 8) & 255) - rstart;
                    *(__nv_bfloat16*)(smb + OFF_S + rr*(SSTRIDE*2) + row*2) = __float2bfloat16(1.0f);
                }
            } else {
                uint4 z = make_uint4(0,0,0,0);
#pragma unroll
                for (int qq = 0; qq < 8; ++qq)
                    *(uint4*)(tb + SWZ((uint32_t)(row*128 + qq*16))) = z;
            }
        }
        __syncthreads();

        for (int ch = 0; ch < nch; ++ch) {
            const int p = ch & 1;
            const uint32_t uP = p ? uT1 : uT0;
            const uint32_t uH = p ? uT0 : uT1;
            const int tHoff = p ? OFF_T0 : OFF_T1;
            const int tPoff = p ? OFF_T1 : OFF_T0;
            const int k = rows[ch*CHUNK] >> 16;
            const uint32_t w1base = uW + (uint32_t)(k*32768);
            const uint32_t w2base = uW + 65536u + (uint32_t)(k*32768);

            float C[16][4];

            // ==== interval 1: GEMM1 + epi1 -> H ; zero S[1-p] ====
            if (ch + 1 < nch) {
                uint32_t* sz = (uint32_t*)(smb + OFF_S + (1-p)*SBYTES);
                for (int i = tid; i < SBYTES/4; i += NTHR) sz[i] = 0;
            }
#pragma unroll
            for (int i = 0; i < 16; ++i) { C[i][0]=0.f; C[i][1]=0.f; C[i][2]=0.f; C[i][3]=0.f; }
#pragma unroll
            for (int kb = 0; kb < 8; ++kb) {
                const uint32_t half16 = (uint32_t)((kb >> 2) * 16384);
                const uint32_t kgrp = (uint32_t)((kb & 3) * 32);
                uint32_t a[4][4];
#pragma unroll
                for (int mt = 0; mt < 4; ++mt) {
                    uint32_t o = (uint32_t)((wm + mt*16 + aRow)*128) + kgrp + aK16;
                    ldsm4(a[mt], uP + half16 + SWZ(o));
                }
                uint32_t bf[2][4];
#pragma unroll
                for (int nt2 = 0; nt2 < 2; ++nt2) {
                    uint32_t o = (uint32_t)((wn + nt2*16 + bRow)*128) + kgrp + bK16;
                    ldsm4(bf[nt2], w1base + half16 + SWZ(o));
                }
#pragma unroll
                for (int mt = 0; mt < 4; ++mt)
#pragma unroll
                    for (int nt = 0; nt < 4; ++nt)
                        mma16816(C[mt*4 + nt], a[mt], &bf[nt >> 1][(nt & 1)*2]);
            }
            {
                char* tb = smb + tHoff + ((wn >> 6) ? 16384 : 0);
#pragma unroll
                for (int mt = 0; mt < 4; ++mt)
#pragma unroll
                    for (int nt = 0; nt < 4; ++nt) {
                        int r0 = wm + mt*16 + g, r1 = r0 + 8;
                        int c = wn + nt*8 + 2*tig;
                        float b0v = sB1[k*HDIM + c], b1v = sB1[k*HDIM + c + 1];
                        float* x = C[mt*4 + nt];
                        uint32_t cb = (uint32_t)((c & 63)*2);
                        *(uint32_t*)(tb + SWZ((uint32_t)(r0*128) + cb)) =
                            packbf(fmaxf(x[0]+b0v,0.f), fmaxf(x[1]+b1v,0.f));
                        *(uint32_t*)(tb + SWZ((uint32_t)(r1*128) + cb)) =
                            packbf(fmaxf(x[2]+b0v,0.f), fmaxf(x[3]+b1v,0.f));
                    }
            }
            __syncthreads();

            // ==== interval 2: GEMM2 + epi2 -> P ====
#pragma unroll
            for (int i = 0; i < 16; ++i) { C[i][0]=0.f; C[i][1]=0.f; C[i][2]=0.f; C[i][3]=0.f; }
#pragma unroll
            for (int kb = 0; kb < 8; ++kb) {
                const uint32_t half16 = (uint32_t)((kb >> 2) * 16384);
                const uint32_t kgrp = (uint32_t)((kb & 3) * 32);
                uint32_t a[4][4];
#pragma unroll
                for (int mt = 0; mt < 4; ++mt) {
                    uint32_t o = (uint32_t)((wm + mt*16 + aRow)*128) + kgrp + aK16;
                    ldsm4(a[mt], uH + half16 + SWZ(o));
                }
                uint32_t bf[2][4];
#pragma unroll
                for (int nt2 = 0; nt2 < 2; ++nt2) {
                    uint32_t o = (uint32_t)((wn + nt2*16 + bRow)*128) + kgrp + bK16;
                    ldsm4(bf[nt2], w2base + half16 + SWZ(o));
                }
#pragma unroll
                for (int mt = 0; mt < 4; ++mt)
#pragma unroll
                    for (int nt = 0; nt < 4; ++nt)
                        mma16816(C[mt*4 + nt], a[mt], &bf[nt >> 1][(nt & 1)*2]);
            }
            {
                char* tb = smb + tPoff + ((wn >> 6) ? 16384 : 0);
#pragma unroll
                for (int mt = 0; mt < 4; ++mt)
#pragma unroll
                    for (int nt = 0; nt < 4; ++nt) {
                        int r0 = wm + mt*16 + g, r1 = r0 + 8;
                        int c = wn + nt*8 + 2*tig;
                        float b0v = sB2[k*HDIM + c], b1v = sB2[k*HDIM + c + 1];
                        float* x = C[mt*4 + nt];
                        uint32_t cb = (uint32_t)((c & 63)*2);
                        *(uint32_t*)(tb + SWZ((uint32_t)(r0*128) + cb)) =
                            packbf(fmaxf(x[0]+b0v,0.f), fmaxf(x[1]+b1v,0.f));
                        *(uint32_t*)(tb + SWZ((uint32_t)(r1*128) + cb)) =
                            packbf(fmaxf(x[2]+b0v,0.f), fmaxf(x[3]+b1v,0.f));
                    }
            }
            __syncthreads();

            // ==== interval 3: agg MMA (S[p] @ m) || gather ch+1 + scatter S[1-p] ====
            {
                const uint32_t uSp = uS + (uint32_t)(p*SBYTES);
#pragma unroll
                for (int kb = 0; kb < 8; ++kb) {
                    uint32_t a[2][4];
#pragma unroll
                    for (int mg = 0; mg < 2; ++mg) {
                        uint32_t ao = uSp + sAbase + (uint32_t)(mg*16*(SSTRIDE*2) + kb*32);
                        asm volatile("ld.shared.b32 %0, [%1];" : "=r"(a[mg][0]) : "r"(ao));
                        asm volatile("ld.shared.b32 %0, [%1];" : "=r"(a[mg][1]) : "r"(ao + 8*(SSTRIDE*2)));
                        asm volatile("ld.shared.b32 %0, [%1];" : "=r"(a[mg][2]) : "r"(ao + 16));
                        asm volatile("ld.shared.b32 %0, [%1];" : "=r"(a[mg][3]) : "r"(ao + 8*(SSTRIDE*2) + 16));
                    }
                    uint32_t bf[4];
                    uint32_t o = (uint32_t)((kb*16 + aggRowL)*128) + aggColL;
                    ldsm4t(bf, uP + aggHalf + SWZ(o));
                    mma16816(Ca[0][0], a[0], bf);
                    mma16816(Ca[0][1], a[0], bf + 2);
                    mma16816(Ca[1][0], a[1], bf);
                    mma16816(Ca[1][1], a[1], bf + 2);
                }
            }
            if (ch + 1 < nch) {
                int row = tid >> 1, hlf = tid & 1;
                int v = rows[(ch+1)*CHUNK + row];
                char* tb = smb + tHoff + hlf*16384;
                if (v >= 0) {
                    int node = hlf ? ((v >> 8) & 255) : (v & 255);
                    const uint4* src = (const uint4*)(smb + OFF_Y + node*FDIM*2);
#pragma unroll
                    for (int qq = 0; qq < 8; ++qq)
                        *(uint4*)(tb + SWZ((uint32_t)(row*128 + qq*16))) = src[qq];
                    if (hlf == 0) {
                        int rr = ((v >> 8) & 255) - rstart;
                        *(__nv_bfloat16*)(smb + OFF_S + (1-p)*SBYTES + rr*(SSTRIDE*2) + row*2) =
                            __float2bfloat16(1.0f);
                    }
                } else {
                    uint4 z = make_uint4(0,0,0,0);
#pragma unroll
                    for (int qq = 0; qq < 8; ++qq)
                        *(uint4*)(tb + SWZ((uint32_t)(row*128 + qq*16))) = z;
                }
            }
            __syncthreads();
        }

        // ---- Ca -> agg (S region), stage W3 -> T0 ----
        {
            float* agg = (float*)(smb + OFF_S);
#pragma unroll
            for (int mg = 0; mg < 2; ++mg)
#pragma unroll
                for (int n8 = 0; n8 < 2; ++n8) {
                    int r0 = mg*16 + g;
                    int c = wid*16 + n8*8 + 2*tig;
                    float* x = Ca[mg][n8];
                    if (r0 < NLOC) {
                        agg[r0*HDIM + c]     = x[0];
                        agg[r0*HDIM + c + 1] = x[1];
                    }
                    if (r0 + 8 < NLOC) {
                        agg[(r0+8)*HDIM + c]     = x[2];
                        agg[(r0+8)*HDIM + c + 1] = x[3];
                    }
                }
        }
        {
            float* w3 = (float*)(smb + OFF_T0);
            for (int i = tid; i < HDIM*FDIM; i += NTHR) w3[i] = W3[i];
        }
        __syncthreads();

        // ---- node phase: kv = tanh(agg/N @ W3 + b3); RK4 stage update ----
        {
            const float dt = sTs[t+1] - sTs[t];
            const float inv_n = 1.0f / (float)NNODE;
            const float* agg = (float*)(smb + OFF_S);
            const float* w3  = (float*)(smb + OFF_T0);
            const float* sb3 = (float*)(smb + OFF_B3);
            for (int idx = tid; idx < NLOC*FDIM; idx += NTHR) {
                int n = idx >> 6, j = idx & 63;
                const float* ar = agg + n*HDIM;
                float acc = 0.f;
#pragma unroll 8
                for (int h = 0; h < HDIM; ++h)
                    acc = fmaf(ar[h], w3[h*FDIM + j], acc);
                float kv = tanhf(acc * inv_n + sb3[j]);
                int gi = (b*NNODE + rstart + n)*FDIM + j;
                float yv = g_y[gi];
                float yin;
                if (stage == 0)      { g_ksum[gi] = kv;        yin = yv + 0.5f*dt*kv; }
                else if (stage == 1) { g_ksum[gi] += 2.f*kv;   yin = yv + 0.5f*dt*kv; }
                else if (stage == 2) { g_ksum[gi] += 2.f*kv;   yin = yv + dt*kv; }
                else {
                    float yn = yv + dt*(1.f/6.f)*(g_ksum[gi] + kv);
                    g_y[gi] = yn;
                    out[(b*NNODE + rstart + n)*(TSTEPS*FDIM) + (t+1)*FDIM + j] = yn;
                    yin = yn;
                }
                g_ybf[gi] = __float2bfloat16(yin);
            }
        }

        // ---- pair barrier: partner's g_ybf must be visible before next stage ----
        __syncthreads();
        __threadfence();
        if (tid == 0) {
            atomicAdd(barp, 1);
            const int target = 2*(iter + 1);
            while (*(volatile int*)barp < target) { }
            __threadfence();
        }
        __syncthreads();
    }
}

// ---------------- launcher ----------------
extern "C" void kernel_launch(void* const* d_in, const int* in_sizes, int n_in,
                              void* d_out, int out_size) {
    const float* fp    = (const float*)d_in[0];
    const float* ts    = (const float*)d_in[1];
    const int*   graph = (const int*)d_in[2];
    const float* W1    = (const float*)d_in[3];
    const float* b1    = (const float*)d_in[4];
    const float* W2    = (const float*)d_in[5];
    const float* b2    = (const float*)d_in[6];
    const float* W3    = (const float*)d_in[7];
    const float* b3    = (const float*)d_in[8];
    float* out = (float*)d_out;

    cudaFuncSetAttribute(persist_kernel, cudaFuncAttributeMaxDynamicSharedMemorySize, SMEM_TOTAL);

    prep_kernel<<<256, 256>>>(fp, W1, W2, out);
    sort_kernel<<<NCTA, 32>>>(graph);
    persist_kernel<<<NCTA, NTHR, SMEM_TOTAL>>>(b1, b2, W3, b3, ts, out);
}

// round 15
// speedup vs baseline: 1.3451x; 1.3059x over previous
#include <cuda_runtime.h>
#include <cuda_bf16.h>
#include <cstdint>

#define BATCH 64
#define NNODE 50
#define FDIM 64
#define HDIM 128
#define EDGES 2450
#define TSTEPS 40
#define CHUNK 128
#define MAXROWS 1408
#define NCTA 128             // 64 batches x 2 halves
#define NTHR 256
#define NLOC 25
#define NSTAGE ((TSTEPS-1)*4)

// ---- smem byte offsets ----
#define OFF_W2  0            // 4 tiles x 16KB = 65536 (W2: k*2+half)
#define OFF_T0  65536        // 32KB: h tile (always); yA during UV; W3 in node phase
#define OFF_T1  98304        // 32KB: m tile (always); W1uv staging during UV
#define OFF_UV  131072       // 4 x 17408 = 69632 (U0,V0,U1,V1: 64 rows x 272B)
#define OFF_B1  200704
#define OFF_B2  201728
#define OFF_B3  202752
#define OFF_TS  203008
#define OFF_S   203264       // 2 x 8704; reused as agg fp32 [25][128]
#define SMEM_TOTAL 220672

#define SWZ(o) ((o) ^ (((o) >> 3) & 0x70))
#define SSTRIDE 136
#define SBYTES 8704
#define UVT 17408            // 64*272

// ---------------- device scratch ----------------
__device__ float          g_y[BATCH*NNODE*FDIM];
__device__ float          g_ksum[BATCH*NNODE*FDIM];
__device__ __nv_bfloat16  g_ybf[BATCH*NNODE*FDIM];
__device__ __nv_bfloat16  g_Wt[8*8192];     // tiles 0-3: W2; 4-7: W1uv (k*2+uv)
__device__ int            g_rows[NCTA*MAXROWS];
__device__ int            g_nrows[NCTA];
__device__ int            g_bar[BATCH];

// ---------------- helpers ----------------
__device__ __forceinline__ void mma16816(float* c, const uint32_t* a, const uint32_t* b) {
    asm volatile(
        "mma.sync.aligned.m16n8k16.row.col.f32.bf16.bf16.f32 "
        "{%0,%1,%2,%3}, {%4,%5,%6,%7}, {%8,%9}, {%0,%1,%2,%3};\n"
        : "+f"(c[0]), "+f"(c[1]), "+f"(c[2]), "+f"(c[3])
        : "r"(a[0]), "r"(a[1]), "r"(a[2]), "r"(a[3]), "r"(b[0]), "r"(b[1]));
}
__device__ __forceinline__ void ldsm4(uint32_t* r, uint32_t addr) {
    asm volatile("ldmatrix.sync.aligned.m8n8.x4.shared.b16 {%0,%1,%2,%3}, [%4];"
                 : "=r"(r[0]), "=r"(r[1]), "=r"(r[2]), "=r"(r[3]) : "r"(addr));
}
__device__ __forceinline__ void ldsm4t(uint32_t* r, uint32_t addr) {
    asm volatile("ldmatrix.sync.aligned.m8n8.x4.trans.shared.b16 {%0,%1,%2,%3}, [%4];"
                 : "=r"(r[0]), "=r"(r[1]), "=r"(r[2]), "=r"(r[3]) : "r"(addr));
}
__device__ __forceinline__ uint32_t smem_u32(const void* p) {
    uint32_t a;
    asm("{ .reg .u64 t; cvta.to.shared.u64 t, %1; cvt.u32.u64 %0, t; }" : "=r"(a) : "l"(p));
    return a;
}
__device__ __forceinline__ uint32_t packbf(float x, float y) {
    __nv_bfloat162 t = __floats2bfloat162_rn(x, y);
    return *reinterpret_cast<uint32_t*>(&t);
}

// ---------------- prep ----------------
__global__ void prep_kernel(const float* __restrict__ fp,
                            const float* __restrict__ W1,
                            const float* __restrict__ W2,
                            float* __restrict__ out) {
    int gsz = gridDim.x * blockDim.x;
    int g0  = blockIdx.x * blockDim.x + threadIdx.x;
    // 8 tiles x 8192 bf16: tiles 0-3 = W2[k][half], tiles 4-7 = W1uv[k][uv]
    for (int i = g0; i < 8*8192; i += gsz) {
        int tile = i >> 13, rem = i & 8191;
        int n = rem >> 6, kk = rem & 63;
        float v;
        if (tile < 4) {
            int k = tile >> 1, half = tile & 1;
            v = W2[k*16384 + (half*64 + kk)*128 + n];
        } else {
            int tt = tile - 4, k = tt >> 1, uv = tt & 1;
            v = W1[k*16384 + (uv*64 + kk)*128 + n];
        }
        g_Wt[tile*8192 + (SWZ((uint32_t)(n*128 + kk*2)) >> 1)] = __float2bfloat16(v);
    }
    for (int i = g0; i < BATCH*NNODE*FDIM; i += gsz) {
        float v = fp[i];
        g_y[i]   = v;
        g_ybf[i] = __float2bfloat16(v);
        out[(i >> 6)*(TSTEPS*FDIM) + (i & 63)] = v;
    }
    for (int i = g0; i < BATCH; i += gsz) g_bar[i] = 0;
}

// ---------------- sort: per-half stable partition by type ----------------
__global__ void sort_kernel(const int* __restrict__ graph) {
    const int cta = blockIdx.x;            // b*2 + hb
    const int b = cta >> 1, hb = cta & 1;
    const int ebase = hb * NLOC * 49;
    const int ecnt  = NLOC * 49;
    const int lane = threadIdx.x;
    int* rows = g_rows + cta * MAXROWS;
    int row = 0;
#pragma unroll
    for (int k = 0; k < 2; ++k) {
        for (int i0 = 0; i0 < ecnt; i0 += 32) {
            int i = i0 + lane;
            bool m = false; int meta = 0;
            if (i < ecnt) {
                int e = ebase + i;
                int kk = graph[b*EDGES + e];
                int r = e / 49, j = e - r*49;
                int s = j + (j >= r);
                meta = (kk << 16) | (r << 8) | s;
                m = (kk == k);
            }
            unsigned mask = __ballot_sync(0xffffffffu, m);
            if (m) rows[row + __popc(mask & ((1u << lane) - 1u))] = meta;
            row += __popc(mask);
        }
        int pad = (128 - (row & 127)) & 127;
        for (int i = lane; i < pad; i += 32) rows[row + i] = -1;
        row += pad;
    }
    if (lane == 0) g_nrows[cta] = row;
}

// gather h tile into T0: h = relu(U_k[s] + V_k[r] + b1[k]) from UV tables
__device__ __forceinline__ void gather_h(char* smb, const int* crow,
                                         int tid, const float* sB1, int rstart,
                                         int sIdx) {
    int row = tid >> 1, hlf = tid & 1;
    int v = crow[row];
    char* tb = smb + OFF_T0 + hlf*16384;
    if (v >= 0) {
        int s = v & 255, r = (v >> 8) & 255, k = v >> 16;
        const uint4* up = (const uint4*)(smb + OFF_UV + (k*2+0)*UVT + s*272 + hlf*128);
        const uint4* vp = (const uint4*)(smb + OFF_UV + (k*2+1)*UVT + r*272 + hlf*128);
        const float* bp = sB1 + k*HDIM + hlf*64;
#pragma unroll
        for (int q = 0; q < 8; ++q) {
            uint4 uu = up[q], vv = vp[q];
            const uint32_t* uw = (const uint32_t*)&uu;
            const uint32_t* vw = (const uint32_t*)&vv;
            uint32_t ow[4];
#pragma unroll
            for (int e = 0; e < 4; ++e) {
                float2 fu = __bfloat1622float2(*(const __nv_bfloat162*)&uw[e]);
                float2 fv = __bfloat1622float2(*(const __nv_bfloat162*)&vw[e]);
                float2 fb = *(const float2*)(bp + q*8 + e*2);
                ow[e] = packbf(fmaxf(fu.x + fv.x + fb.x, 0.f),
                               fmaxf(fu.y + fv.y + fb.y, 0.f));
            }
            *(uint4*)(tb + SWZ((uint32_t)(row*128 + q*16))) =
                make_uint4(ow[0], ow[1], ow[2], ow[3]);
        }
        if (hlf == 0) {
            int rr = r - rstart;
            *(__nv_bfloat16*)(smb + OFF_S + sIdx*SBYTES + rr*(SSTRIDE*2) + row*2) =
                __float2bfloat16(1.0f);
        }
    } else {
        uint4 z = make_uint4(0,0,0,0);
#pragma unroll
        for (int q = 0; q < 8; ++q)
            *(uint4*)(tb + SWZ((uint32_t)(row*128 + q*16))) = z;
    }
}

// ---------------- persistent fused kernel ----------------
__global__ void __launch_bounds__(NTHR, 1)
persist_kernel(const float* __restrict__ b1f, const float* __restrict__ b2f,
               const float* __restrict__ W3,  const float* __restrict__ b3f,
               const float* __restrict__ tsp, float* __restrict__ out) {
    extern __shared__ char smb[];
    const int tid  = threadIdx.x;
    const int lane = tid & 31, wid = tid >> 5;   // 8 warps
    const int cta  = blockIdx.x;
    const int b = cta >> 1, hb = cta & 1;
    const int rstart = hb * NLOC;
    int* const barp = &g_bar[b];

    // ---- one-time: W2 (64KB), biases, ts ----
    {
        const uint4* src = reinterpret_cast<const uint4*>(g_Wt);
        uint4* dst = reinterpret_cast<uint4*>(smb + OFF_W2);
        for (int i = tid; i < 65536/16; i += NTHR) dst[i] = src[i];
    }
    ((float*)(smb + OFF_B1))[tid] = b1f[tid];
    ((float*)(smb + OFF_B2))[tid] = b2f[tid];
    if (tid < 64) ((float*)(smb + OFF_B3))[tid] = b3f[tid];
    if (tid < TSTEPS) ((float*)(smb + OFF_TS))[tid] = tsp[tid];

    const float* sB1 = (float*)(smb + OFF_B1);
    const float* sB2 = (float*)(smb + OFF_B2);
    const float* sTs = (float*)(smb + OFF_TS);

    const int nch = g_nrows[cta] >> 7;
    const int* __restrict__ rows = g_rows + cta * MAXROWS;

    // main-GEMM warp tiling: 2M x 4N of 64x32 tiles
    const int wm = (wid & 1) * 64;
    const int wn = (wid >> 1) * 32;
    const int g = lane >> 2, tig = lane & 3;
    const int li = lane & 7, lm = lane >> 3;
    const int aRow = (lm & 1)*8 + li;
    const int aK16 = (lm >> 1) * 16;
    const int bRow = (lm >> 1)*8 + li;
    const int bK16 = (lm & 1) * 16;

    const uint32_t uT0 = smem_u32(smb + OFF_T0);
    const uint32_t uT1 = smem_u32(smb + OFF_T1);
    const uint32_t uW2 = smem_u32(smb + OFF_W2);
    const uint32_t uS  = smem_u32(smb + OFF_S);

    const uint32_t aggHalf = (wid >= 4) ? 16384u : 0u;
    const uint32_t aggRowL = (uint32_t)((lm & 1)*8 + li);
    const uint32_t aggColL = (uint32_t)(((wid & 3)*16 + (lm >> 1)*8) * 2);
    const uint32_t sAbase = (uint32_t)(g*(SSTRIDE*2) + 2*tig*2);

    // UV-GEMM warp mapping: uvW in {0,1}, n-quarter nq in {0..3}
    const int uvW = wid >> 2;
    const int nq  = wid & 3;

    for (int iter = 0; iter < NSTAGE; ++iter) {
        const int t = iter >> 2, stage = iter & 3;

        // ---- stage setup: build yA tile in T0 (64x64 bf16, SW128); zero S[0] ----
        {
            const uint4* src = (const uint4*)(g_ybf + b*NNODE*FDIM);
            for (int i = tid; i < 512; i += NTHR) {
                int row = i >> 3, q = i & 7;
                uint4 val = make_uint4(0,0,0,0);
                if (row < NNODE) val = src[row*8 + q];
                *(uint4*)(smb + OFF_T0 + SWZ((uint32_t)(row*128 + q*16))) = val;
            }
            uint32_t* s0 = (uint32_t*)(smb + OFF_S);
            for (int i = tid; i < SBYTES/4; i += NTHR) s0[i] = 0;
        }
        __syncthreads();

        // ---- UV passes: U_k = y@W1_send, V_k = y@W1_recv ----
#pragma unroll
        for (int kpass = 0; kpass < 2; ++kpass) {
            {
                const uint4* src = (const uint4*)(g_Wt + (4 + kpass*2)*8192);
                uint4* dst = (uint4*)(smb + OFF_T1);
                for (int i = tid; i < 2048; i += NTHR) dst[i] = src[i];
            }
            __syncthreads();
            {
                float C[16][4];
#pragma unroll
                for (int i = 0; i < 16; ++i) { C[i][0]=0.f; C[i][1]=0.f; C[i][2]=0.f; C[i][3]=0.f; }
#pragma unroll
                for (int kb = 0; kb < 4; ++kb) {
                    uint32_t a[4][4];
#pragma unroll
                    for (int mt = 0; mt < 4; ++mt) {
                        uint32_t o = (uint32_t)((mt*16 + aRow)*128) + (uint32_t)(kb*32) + aK16;
                        ldsm4(a[mt], uT0 + SWZ(o));
                    }
                    uint32_t bf[2][4];
#pragma unroll
                    for (int nt2 = 0; nt2 < 2; ++nt2) {
                        uint32_t o = (uint32_t)((nq*32 + nt2*16 + bRow)*128) + (uint32_t)(kb*32) + bK16;
                        ldsm4(bf[nt2], uT1 + (uint32_t)(uvW*16384) + SWZ(o));
                    }
#pragma unroll
                    for (int mt = 0; mt < 4; ++mt)
#pragma unroll
                        for (int nt = 0; nt < 4; ++nt)
                            mma16816(C[mt*4 + nt], a[mt], &bf[nt >> 1][(nt & 1)*2]);
                }
                // epilogue: raw U/V bf16 rows (stride 272B)
                char* base = smb + OFF_UV + (kpass*2 + uvW)*UVT;
#pragma unroll
                for (int mt = 0; mt < 4; ++mt)
#pragma unroll
                    for (int nt = 0; nt < 4; ++nt) {
                        int r0 = mt*16 + g, r1 = r0 + 8;
                        int c = nq*32 + nt*8 + 2*tig;
                        float* x = C[mt*4 + nt];
                        *(uint32_t*)(base + r0*272 + c*2) = packbf(x[0], x[1]);
                        *(uint32_t*)(base + r1*272 + c*2) = packbf(x[2], x[3]);
                    }
            }
            __syncthreads();
        }

        // ---- prologue: gather h chunk0 -> T0, scatter S[0] ----
        gather_h(smb, rows, tid, sB1, rstart, 0);
        float Ca[2][2][4];
#pragma unroll
        for (int i = 0; i < 2; ++i)
#pragma unroll
            for (int j = 0; j < 2; ++j) { Ca[i][j][0]=0.f; Ca[i][j][1]=0.f; Ca[i][j][2]=0.f; Ca[i][j][3]=0.f; }
        __syncthreads();

        // ---- chunk loop: h always in T0, m always in T1; 2 syncs/chunk ----
        for (int ch = 0; ch < nch; ++ch) {
            const int p = ch & 1;
            const int k = rows[ch*CHUNK] >> 16;
            const uint32_t w2base = uW2 + (uint32_t)(k*32768);

            // ==== interval 1: zero S[1-p]; GEMM2 (A=h from T0); epi -> m in T1 ====
            if (ch + 1 < nch) {
                uint32_t* sz = (uint32_t*)(smb + OFF_S + (1-p)*SBYTES);
                for (int i = tid; i < SBYTES/4; i += NTHR) sz[i] = 0;
            }
            float C[16][4];
#pragma unroll
            for (int i = 0; i < 16; ++i) { C[i][0]=0.f; C[i][1]=0.f; C[i][2]=0.f; C[i][3]=0.f; }
#pragma unroll
            for (int kb = 0; kb < 8; ++kb) {
                const uint32_t half16 = (uint32_t)((kb >> 2) * 16384);
                const uint32_t kgrp = (uint32_t)((kb & 3) * 32);
                uint32_t a[4][4];
#pragma unroll
                for (int mt = 0; mt < 4; ++mt) {
                    uint32_t o = (uint32_t)((wm + mt*16 + aRow)*128) + kgrp + aK16;
                    ldsm4(a[mt], uT0 + half16 + SWZ(o));
                }
                uint32_t bf[2][4];
#pragma unroll
                for (int nt2 = 0; nt2 < 2; ++nt2) {
                    uint32_t o = (uint32_t)((wn + nt2*16 + bRow)*128) + kgrp + bK16;
                    ldsm4(bf[nt2], w2base + half16 + SWZ(o));
                }
#pragma unroll
                for (int mt = 0; mt < 4; ++mt)
#pragma unroll
                    for (int nt = 0; nt < 4; ++nt)
                        mma16816(C[mt*4 + nt], a[mt], &bf[nt >> 1][(nt & 1)*2]);
            }
            {
                char* tb = smb + OFF_T1 + ((wn >> 6) ? 16384 : 0);
#pragma unroll
                for (int mt = 0; mt < 4; ++mt)
#pragma unroll
                    for (int nt = 0; nt < 4; ++nt) {
                        int r0 = wm + mt*16 + g, r1 = r0 + 8;
                        int c = wn + nt*8 + 2*tig;
                        float b0v = sB2[k*HDIM + c], b1v = sB2[k*HDIM + c + 1];
                        float* x = C[mt*4 + nt];
                        uint32_t cb = (uint32_t)((c & 63)*2);
                        *(uint32_t*)(tb + SWZ((uint32_t)(r0*128) + cb)) =
                            packbf(fmaxf(x[0]+b0v,0.f), fmaxf(x[1]+b1v,0.f));
                        *(uint32_t*)(tb + SWZ((uint32_t)(r1*128) + cb)) =
                            packbf(fmaxf(x[2]+b0v,0.f), fmaxf(x[3]+b1v,0.f));
                    }
            }
            __syncthreads();

            // ==== interval 2: agg MMA (S[p] @ m in T1) || gather h_{ch+1} -> T0 ====
            {
                const uint32_t uSp = uS + (uint32_t)(p*SBYTES);
#pragma unroll
                for (int kb = 0; kb < 8; ++kb) {
                    uint32_t a[2][4];
#pragma unroll
                    for (int mg = 0; mg < 2; ++mg) {
                        uint32_t ao = uSp + sAbase + (uint32_t)(mg*16*(SSTRIDE*2) + kb*32);
                        asm volatile("ld.shared.b32 %0, [%1];" : "=r"(a[mg][0]) : "r"(ao));
                        asm volatile("ld.shared.b32 %0, [%1];" : "=r"(a[mg][1]) : "r"(ao + 8*(SSTRIDE*2)));
                        asm volatile("ld.shared.b32 %0, [%1];" : "=r"(a[mg][2]) : "r"(ao + 16));
                        asm volatile("ld.shared.b32 %0, [%1];" : "=r"(a[mg][3]) : "r"(ao + 8*(SSTRIDE*2) + 16));
                    }
                    uint32_t bf[4];
                    uint32_t o = (uint32_t)((kb*16 + aggRowL)*128) + aggColL;
                    ldsm4t(bf, uT1 + aggHalf + SWZ(o));
                    mma16816(Ca[0][0], a[0], bf);
                    mma16816(Ca[0][1], a[0], bf + 2);
                    mma16816(Ca[1][0], a[1], bf);
                    mma16816(Ca[1][1], a[1], bf + 2);
                }
            }
            if (ch + 1 < nch)
                gather_h(smb, rows + (ch+1)*CHUNK, tid, sB1, rstart, 1-p);
            __syncthreads();
        }

        // ---- Ca -> agg (S region), stage W3 -> T0 ----
        {
            float* agg = (float*)(smb + OFF_S);
#pragma unroll
            for (int mg = 0; mg < 2; ++mg)
#pragma unroll
                for (int n8 = 0; n8 < 2; ++n8) {
                    int r0 = mg*16 + g;
                    int c = wid*16 + n8*8 + 2*tig;
                    float* x = Ca[mg][n8];
                    if (r0 < NLOC) {
                        agg[r0*HDIM + c]     = x[0];
                        agg[r0*HDIM + c + 1] = x[1];
                    }
                    if (r0 + 8 < NLOC) {
                        agg[(r0+8)*HDIM + c]     = x[2];
                        agg[(r0+8)*HDIM + c + 1] = x[3];
                    }
                }
        }
        {
            float* w3 = (float*)(smb + OFF_T0);
            for (int i = tid; i < HDIM*FDIM; i += NTHR) w3[i] = W3[i];
        }
        __syncthreads();

        // ---- node phase: kv = tanh(agg/N @ W3 + b3); RK4 update ----
        {
            const float dt = sTs[t+1] - sTs[t];
            const float inv_n = 1.0f / (float)NNODE;
            const float* agg = (float*)(smb + OFF_S);
            const float* w3  = (float*)(smb + OFF_T0);
            const float* sb3 = (float*)(smb + OFF_B3);
            for (int idx = tid; idx < NLOC*FDIM; idx += NTHR) {
                int n = idx >> 6, j = idx & 63;
                const float* ar = agg + n*HDIM;
                float acc = 0.f;
#pragma unroll 8
                for (int h = 0; h < HDIM; ++h)
                    acc = fmaf(ar[h], w3[h*FDIM + j], acc);
                float kv = tanhf(acc * inv_n + sb3[j]);
                int gi = (b*NNODE + rstart + n)*FDIM + j;
                float yv = g_y[gi];
                float yin;
                if (stage == 0)      { g_ksum[gi] = kv;        yin = yv + 0.5f*dt*kv; }
                else if (stage == 1) { g_ksum[gi] += 2.f*kv;   yin = yv + 0.5f*dt*kv; }
                else if (stage == 2) { g_ksum[gi] += 2.f*kv;   yin = yv + dt*kv; }
                else {
                    float yn = yv + dt*(1.f/6.f)*(g_ksum[gi] + kv);
                    g_y[gi] = yn;
                    out[(b*NNODE + rstart + n)*(TSTEPS*FDIM) + (t+1)*FDIM + j] = yn;
                    yin = yn;
                }
                g_ybf[gi] = __float2bfloat16(yin);
            }
        }

        // ---- pair barrier ----
        __syncthreads();
        __threadfence();
        if (tid == 0) {
            atomicAdd(barp, 1);
            const int target = 2*(iter + 1);
            while (*(volatile int*)barp < target) { }
            __threadfence();
        }
        __syncthreads();
    }
}

// ---------------- launcher ----------------
extern "C" void kernel_launch(void* const* d_in, const int* in_sizes, int n_in,
                              void* d_out, int out_size) {
    const float* fp    = (const float*)d_in[0];
    const float* ts    = (const float*)d_in[1];
    const int*   graph = (const int*)d_in[2];
    const float* W1    = (const float*)d_in[3];
    const float* b1    = (const float*)d_in[4];
    const float* W2    = (const float*)d_in[5];
    const float* b2    = (const float*)d_in[6];
    const float* W3    = (const float*)d_in[7];
    const float* b3    = (const float*)d_in[8];
    float* out = (float*)d_out;

    cudaFuncSetAttribute(persist_kernel, cudaFuncAttributeMaxDynamicSharedMemorySize, SMEM_TOTAL);

    prep_kernel<<<256, 256>>>(fp, W1, W2, out);
    sort_kernel<<<NCTA, 32>>>(graph);
    persist_kernel<<<NCTA, NTHR, SMEM_TOTAL>>>(b1, b2, W3, b3, ts, out);
}

// round 16
// speedup vs baseline: 1.4210x; 1.0564x over previous
#include <cuda_runtime.h>
#include <cuda_bf16.h>
#include <cstdint>

#define BATCH 64
#define NNODE 50
#define FDIM 64
#define HDIM 128
#define EDGES 2450
#define TSTEPS 40
#define CHUNK 128
#define MAXROWS 1408
#define NCTA 128             // 64 batches x 2 halves
#define NTHR 512
#define NLOC 25
#define NSTAGE ((TSTEPS-1)*4)

// ---- smem byte offsets ----
#define OFF_W2  0            // 4 tiles x 16KB = 65536 (W2: k*2+half)
#define OFF_T0  65536        // 32KB: h tile; yA during UV; W3 in node phase
#define OFF_T1  98304        // 32KB: m tile; W1uv staging during UV
#define OFF_UV  131072       // 4 x 17408 = 69632 (U0,V0,U1,V1: 64 rows x 272B)
#define OFF_B1  200704
#define OFF_B2  201728
#define OFF_B3  202752
#define OFF_TS  203008
#define OFF_S   203264       // 2 x 8704; reused as agg fp32 [25][128]
#define SMEM_TOTAL 220672

#define SWZ(o) ((o) ^ (((o) >> 3) & 0x70))
#define SSTRIDE 136
#define SBYTES 8704
#define UVT 17408            // 64*272

// ---------------- device scratch ----------------
__device__ float          g_y[BATCH*NNODE*FDIM];
__device__ float          g_ksum[BATCH*NNODE*FDIM];
__device__ __nv_bfloat16  g_ybf[BATCH*NNODE*FDIM];
__device__ __nv_bfloat16  g_Wt[8*8192];     // tiles 0-3: W2; 4-7: W1uv (k*2+uv)
__device__ int            g_rows[NCTA*MAXROWS];
__device__ int            g_nrows[NCTA];
__device__ int            g_bar[BATCH];

// ---------------- helpers ----------------
__device__ __forceinline__ void mma16816(float* c, const uint32_t* a, const uint32_t* b) {
    asm volatile(
        "mma.sync.aligned.m16n8k16.row.col.f32.bf16.bf16.f32 "
        "{%0,%1,%2,%3}, {%4,%5,%6,%7}, {%8,%9}, {%0,%1,%2,%3};\n"
        : "+f"(c[0]), "+f"(c[1]), "+f"(c[2]), "+f"(c[3])
        : "r"(a[0]), "r"(a[1]), "r"(a[2]), "r"(a[3]), "r"(b[0]), "r"(b[1]));
}
__device__ __forceinline__ void ldsm4(uint32_t* r, uint32_t addr) {
    asm volatile("ldmatrix.sync.aligned.m8n8.x4.shared.b16 {%0,%1,%2,%3}, [%4];"
                 : "=r"(r[0]), "=r"(r[1]), "=r"(r[2]), "=r"(r[3]) : "r"(addr));
}
__device__ __forceinline__ void ldsm4t(uint32_t* r, uint32_t addr) {
    asm volatile("ldmatrix.sync.aligned.m8n8.x4.trans.shared.b16 {%0,%1,%2,%3}, [%4];"
                 : "=r"(r[0]), "=r"(r[1]), "=r"(r[2]), "=r"(r[3]) : "r"(addr));
}
__device__ __forceinline__ uint32_t smem_u32(const void* p) {
    uint32_t a;
    asm("{ .reg .u64 t; cvta.to.shared.u64 t, %1; cvt.u32.u64 %0, t; }" : "=r"(a) : "l"(p));
    return a;
}
__device__ __forceinline__ uint32_t packbf(float x, float y) {
    __nv_bfloat162 t = __floats2bfloat162_rn(x, y);
    return *reinterpret_cast<uint32_t*>(&t);
}

// ---------------- prep ----------------
__global__ void prep_kernel(const float* __restrict__ fp,
                            const float* __restrict__ W1,
                            const float* __restrict__ W2,
                            float* __restrict__ out) {
    int gsz = gridDim.x * blockDim.x;
    int g0  = blockIdx.x * blockDim.x + threadIdx.x;
    // 8 tiles x 8192 bf16: tiles 0-3 = W2[k][half], tiles 4-7 = W1uv[k][uv]
    for (int i = g0; i < 8*8192; i += gsz) {
        int tile = i >> 13, rem = i & 8191;
        int n = rem >> 6, kk = rem & 63;
        float v;
        if (tile < 4) {
            int k = tile >> 1, half = tile & 1;
            v = W2[k*16384 + (half*64 + kk)*128 + n];
        } else {
            int tt = tile - 4, k = tt >> 1, uv = tt & 1;
            v = W1[k*16384 + (uv*64 + kk)*128 + n];
        }
        g_Wt[tile*8192 + (SWZ((uint32_t)(n*128 + kk*2)) >> 1)] = __float2bfloat16(v);
    }
    for (int i = g0; i < BATCH*NNODE*FDIM; i += gsz) {
        float v = fp[i];
        g_y[i]   = v;
        g_ybf[i] = __float2bfloat16(v);
        out[(i >> 6)*(TSTEPS*FDIM) + (i & 63)] = v;
    }
    for (int i = g0; i < BATCH; i += gsz) g_bar[i] = 0;
}

// ---------------- sort: per-half stable partition by type ----------------
__global__ void sort_kernel(const int* __restrict__ graph) {
    const int cta = blockIdx.x;            // b*2 + hb
    const int b = cta >> 1, hb = cta & 1;
    const int ebase = hb * NLOC * 49;
    const int ecnt  = NLOC * 49;
    const int lane = threadIdx.x;
    int* rows = g_rows + cta * MAXROWS;
    int row = 0;
#pragma unroll
    for (int k = 0; k < 2; ++k) {
        for (int i0 = 0; i0 < ecnt; i0 += 32) {
            int i = i0 + lane;
            bool m = false; int meta = 0;
            if (i < ecnt) {
                int e = ebase + i;
                int kk = graph[b*EDGES + e];
                int r = e / 49, j = e - r*49;
                int s = j + (j >= r);
                meta = (kk << 16) | (r << 8) | s;
                m = (kk == k);
            }
            unsigned mask = __ballot_sync(0xffffffffu, m);
            if (m) rows[row + __popc(mask & ((1u << lane) - 1u))] = meta;
            row += __popc(mask);
        }
        int pad = (128 - (row & 127)) & 127;
        for (int i = lane; i < pad; i += 32) rows[row + i] = -1;
        row += pad;
    }
    if (lane == 0) g_nrows[cta] = row;
}

// gather h tile into T0: h = relu(U_k[s] + V_k[r] + b1[k]) from UV tables
// (tid256 in [0,256): row = tid256>>1, half = tid256&1)
__device__ __forceinline__ void gather_h(char* smb, const int* crow,
                                         int tid256, const float* sB1, int rstart,
                                         int sIdx) {
    int row = tid256 >> 1, hlf = tid256 & 1;
    int v = crow[row];
    char* tb = smb + OFF_T0 + hlf*16384;
    if (v >= 0) {
        int s = v & 255, r = (v >> 8) & 255, k = v >> 16;
        const uint4* up = (const uint4*)(smb + OFF_UV + (k*2+0)*UVT + s*272 + hlf*128);
        const uint4* vp = (const uint4*)(smb + OFF_UV + (k*2+1)*UVT + r*272 + hlf*128);
        const float* bp = sB1 + k*HDIM + hlf*64;
#pragma unroll
        for (int q = 0; q < 8; ++q) {
            uint4 uu = up[q], vv = vp[q];
            const uint32_t* uw = (const uint32_t*)&uu;
            const uint32_t* vw = (const uint32_t*)&vv;
            uint32_t ow[4];
#pragma unroll
            for (int e = 0; e < 4; ++e) {
                float2 fu = __bfloat1622float2(*(const __nv_bfloat162*)&uw[e]);
                float2 fv = __bfloat1622float2(*(const __nv_bfloat162*)&vw[e]);
                float2 fb = *(const float2*)(bp + q*8 + e*2);
                ow[e] = packbf(fmaxf(fu.x + fv.x + fb.x, 0.f),
                               fmaxf(fu.y + fv.y + fb.y, 0.f));
            }
            *(uint4*)(tb + SWZ((uint32_t)(row*128 + q*16))) =
                make_uint4(ow[0], ow[1], ow[2], ow[3]);
        }
        if (hlf == 0) {
            int rr = r - rstart;
            *(__nv_bfloat16*)(smb + OFF_S + sIdx*SBYTES + rr*(SSTRIDE*2) + row*2) =
                __float2bfloat16(1.0f);
        }
    } else {
        uint4 z = make_uint4(0,0,0,0);
#pragma unroll
        for (int q = 0; q < 8; ++q)
            *(uint4*)(tb + SWZ((uint32_t)(row*128 + q*16))) = z;
    }
}

// ---------------- persistent fused kernel: 512 threads, 16 warps ----------------
__global__ void __launch_bounds__(NTHR, 1)
persist_kernel(const float* __restrict__ b1f, const float* __restrict__ b2f,
               const float* __restrict__ W3,  const float* __restrict__ b3f,
               const float* __restrict__ tsp, float* __restrict__ out) {
    extern __shared__ char smb[];
    const int tid  = threadIdx.x;
    const int lane = tid & 31, wid = tid >> 5;   // 16 warps
    const int cta  = blockIdx.x;
    const int b = cta >> 1, hb = cta & 1;
    const int rstart = hb * NLOC;
    int* const barp = &g_bar[b];

    // ---- one-time: W2 (64KB), biases, ts ----
    {
        const uint4* src = reinterpret_cast<const uint4*>(g_Wt);
        uint4* dst = reinterpret_cast<uint4*>(smb + OFF_W2);
        for (int i = tid; i < 65536/16; i += NTHR) dst[i] = src[i];
    }
    if (tid < 256) {
        ((float*)(smb + OFF_B1))[tid] = b1f[tid];
        ((float*)(smb + OFF_B2))[tid] = b2f[tid];
    }
    if (tid < 64) ((float*)(smb + OFF_B3))[tid] = b3f[tid];
    if (tid < TSTEPS) ((float*)(smb + OFF_TS))[tid] = tsp[tid];

    const float* sB1 = (float*)(smb + OFF_B1);
    const float* sB2 = (float*)(smb + OFF_B2);
    const float* sTs = (float*)(smb + OFF_TS);

    const int nch = g_nrows[cta] >> 7;
    const int* __restrict__ rows = g_rows + cta * MAXROWS;

    // GEMM2 warp tiling: 4M x 4N of 32x32 tiles
    const int wm = (wid & 3) * 32;
    const int wn = (wid >> 2) * 32;
    const int g = lane >> 2, tig = lane & 3;
    const int li = lane & 7, lm = lane >> 3;
    const int aRow = (lm & 1)*8 + li;
    const int aK16 = (lm >> 1) * 16;
    const int bRow = (lm >> 1)*8 + li;
    const int bK16 = (lm & 1) * 16;

    const uint32_t uT0 = smem_u32(smb + OFF_T0);
    const uint32_t uT1 = smem_u32(smb + OFF_T1);
    const uint32_t uW2 = smem_u32(smb + OFF_W2);
    const uint32_t uS  = smem_u32(smb + OFF_S);

    // agg-MMA (warps 0-7): warp owns m cols wid*16..+15
    const uint32_t aggHalf = (wid >= 4) ? 16384u : 0u;
    const uint32_t aggRowL = (uint32_t)((lm & 1)*8 + li);
    const uint32_t aggColL = (uint32_t)(((wid & 3)*16 + (lm >> 1)*8) * 2);
    const uint32_t sAbase = (uint32_t)(g*(SSTRIDE*2) + 2*tig*2);

    // UV pass mapping: uv = wid>>3 (0=U send, 1=V recv), nq8 = wid&7 (16-col group)
    const int uv  = wid >> 3;
    const int nq8 = wid & 7;

    for (int iter = 0; iter < NSTAGE; ++iter) {
        const int t = iter >> 2, stage = iter & 3;

        // ---- stage setup: yA tile -> T0 (64x64 bf16 SW128); zero S[0] ----
        {
            const uint4* src = (const uint4*)(g_ybf + b*NNODE*FDIM);
            for (int i = tid; i < 512; i += NTHR) {
                int row = i >> 3, q = i & 7;
                uint4 val = make_uint4(0,0,0,0);
                if (row < NNODE) val = src[row*8 + q];
                *(uint4*)(smb + OFF_T0 + SWZ((uint32_t)(row*128 + q*16))) = val;
            }
            uint32_t* s0 = (uint32_t*)(smb + OFF_S);
            for (int i = tid; i < SBYTES/4; i += NTHR) s0[i] = 0;
        }
        __syncthreads();

        // ---- UV passes: one per k; warps 0-7 compute U_k, warps 8-15 V_k ----
#pragma unroll
        for (int kpass = 0; kpass < 2; ++kpass) {
            {
                const uint4* src = (const uint4*)(g_Wt + (4 + kpass*2)*8192);
                uint4* dst = (uint4*)(smb + OFF_T1);
                for (int i = tid; i < 2048; i += NTHR) dst[i] = src[i];
            }
            __syncthreads();
            {
                float C[8][4];
#pragma unroll
                for (int i = 0; i < 8; ++i) { C[i][0]=0.f; C[i][1]=0.f; C[i][2]=0.f; C[i][3]=0.f; }
#pragma unroll
                for (int kb = 0; kb < 4; ++kb) {
                    uint32_t a[4][4];
#pragma unroll
                    for (int mt = 0; mt < 4; ++mt) {
                        uint32_t o = (uint32_t)((mt*16 + aRow)*128) + (uint32_t)(kb*32) + aK16;
                        ldsm4(a[mt], uT0 + SWZ(o));
                    }
                    uint32_t bf[4];
                    {
                        uint32_t o = (uint32_t)((nq8*16 + bRow)*128) + (uint32_t)(kb*32) + bK16;
                        ldsm4(bf, uT1 + (uint32_t)(uv*16384) + SWZ(o));
                    }
#pragma unroll
                    for (int mt = 0; mt < 4; ++mt)
#pragma unroll
                        for (int nt = 0; nt < 2; ++nt)
                            mma16816(C[mt*2 + nt], a[mt], &bf[nt*2]);
                }
                // epilogue: raw U/V bf16 rows (stride 272B)
                char* base = smb + OFF_UV + (kpass*2 + uv)*UVT;
#pragma unroll
                for (int mt = 0; mt < 4; ++mt)
#pragma unroll
                    for (int nt = 0; nt < 2; ++nt) {
                        int r0 = mt*16 + g, r1 = r0 + 8;
                        int c = nq8*16 + nt*8 + 2*tig;
                        float* x = C[mt*2 + nt];
                        *(uint32_t*)(base + r0*272 + c*2) = packbf(x[0], x[1]);
                        *(uint32_t*)(base + r1*272 + c*2) = packbf(x[2], x[3]);
                    }
            }
            __syncthreads();
        }

        // ---- prologue: gather h chunk0 -> T0, scatter S[0] ----
        if (tid < 256) gather_h(smb, rows, tid, sB1, rstart, 0);
        float Ca[2][2][4];
#pragma unroll
        for (int i = 0; i < 2; ++i)
#pragma unroll
            for (int j = 0; j < 2; ++j) { Ca[i][j][0]=0.f; Ca[i][j][1]=0.f; Ca[i][j][2]=0.f; Ca[i][j][3]=0.f; }
        __syncthreads();

        // ---- chunk loop: h in T0, m in T1; 2 syncs/chunk ----
        for (int ch = 0; ch < nch; ++ch) {
            const int p = ch & 1;
            const int k = rows[ch*CHUNK] >> 16;
            const uint32_t w2base = uW2 + (uint32_t)(k*32768);

            // ==== interval 1: zero S[1-p]; GEMM2 (A=h in T0); epi -> m in T1 ====
            if (ch + 1 < nch) {
                uint32_t* sz = (uint32_t*)(smb + OFF_S + (1-p)*SBYTES);
                for (int i = tid; i < SBYTES/4; i += NTHR) sz[i] = 0;
            }
            float C[8][4];
#pragma unroll
            for (int i = 0; i < 8; ++i) { C[i][0]=0.f; C[i][1]=0.f; C[i][2]=0.f; C[i][3]=0.f; }
#pragma unroll
            for (int kb = 0; kb < 8; ++kb) {
                const uint32_t half16 = (uint32_t)((kb >> 2) * 16384);
                const uint32_t kgrp = (uint32_t)((kb & 3) * 32);
                uint32_t a[2][4];
#pragma unroll
                for (int mt = 0; mt < 2; ++mt) {
                    uint32_t o = (uint32_t)((wm + mt*16 + aRow)*128) + kgrp + aK16;
                    ldsm4(a[mt], uT0 + half16 + SWZ(o));
                }
                uint32_t bf[2][4];
#pragma unroll
                for (int nt2 = 0; nt2 < 2; ++nt2) {
                    uint32_t o = (uint32_t)((wn + nt2*16 + bRow)*128) + kgrp + bK16;
                    ldsm4(bf[nt2], w2base + half16 + SWZ(o));
                }
#pragma unroll
                for (int mt = 0; mt < 2; ++mt)
#pragma unroll
                    for (int nt = 0; nt < 4; ++nt)
                        mma16816(C[mt*4 + nt], a[mt], &bf[nt >> 1][(nt & 1)*2]);
            }
            {
                char* tb = smb + OFF_T1 + ((wn >= 64) ? 16384 : 0);
#pragma unroll
                for (int mt = 0; mt < 2; ++mt)
#pragma unroll
                    for (int nt = 0; nt < 4; ++nt) {
                        int r0 = wm + mt*16 + g, r1 = r0 + 8;
                        int c = wn + nt*8 + 2*tig;
                        float b0v = sB2[k*HDIM + c], b1v = sB2[k*HDIM + c + 1];
                        float* x = C[mt*4 + nt];
                        uint32_t cb = (uint32_t)((c & 63)*2);
                        *(uint32_t*)(tb + SWZ((uint32_t)(r0*128) + cb)) =
                            packbf(fmaxf(x[0]+b0v,0.f), fmaxf(x[1]+b1v,0.f));
                        *(uint32_t*)(tb + SWZ((uint32_t)(r1*128) + cb)) =
                            packbf(fmaxf(x[2]+b0v,0.f), fmaxf(x[3]+b1v,0.f));
                    }
            }
            __syncthreads();

            // ==== interval 2: warps 0-7 agg MMA (S[p] @ m) ; warps 8-15 gather ch+1 ====
            if (wid < 8) {
                const uint32_t uSp = uS + (uint32_t)(p*SBYTES);
#pragma unroll
                for (int kb = 0; kb < 8; ++kb) {
                    uint32_t a[2][4];
#pragma unroll
                    for (int mg = 0; mg < 2; ++mg) {
                        uint32_t ao = uSp + sAbase + (uint32_t)(mg*16*(SSTRIDE*2) + kb*32);
                        asm volatile("ld.shared.b32 %0, [%1];" : "=r"(a[mg][0]) : "r"(ao));
                        asm volatile("ld.shared.b32 %0, [%1];" : "=r"(a[mg][1]) : "r"(ao + 8*(SSTRIDE*2)));
                        asm volatile("ld.shared.b32 %0, [%1];" : "=r"(a[mg][2]) : "r"(ao + 16));
                        asm volatile("ld.shared.b32 %0, [%1];" : "=r"(a[mg][3]) : "r"(ao + 8*(SSTRIDE*2) + 16));
                    }
                    uint32_t bf[4];
                    uint32_t o = (uint32_t)((kb*16 + aggRowL)*128) + aggColL;
                    ldsm4t(bf, uT1 + aggHalf + SWZ(o));
                    mma16816(Ca[0][0], a[0], bf);
                    mma16816(Ca[0][1], a[0], bf + 2);
                    mma16816(Ca[1][0], a[1], bf);
                    mma16816(Ca[1][1], a[1], bf + 2);
                }
            } else if (ch + 1 < nch) {
                gather_h(smb, rows + (ch+1)*CHUNK, tid - 256, sB1, rstart, 1-p);
            }
            __syncthreads();
        }

        // ---- Ca -> agg (S region, warps 0-7), stage W3 -> T0 ----
        if (wid < 8) {
            float* agg = (float*)(smb + OFF_S);
#pragma unroll
            for (int mg = 0; mg < 2; ++mg)
#pragma unroll
                for (int n8 = 0; n8 < 2; ++n8) {
                    int r0 = mg*16 + g;
                    int c = wid*16 + n8*8 + 2*tig;
                    float* x = Ca[mg][n8];
                    if (r0 < NLOC) {
                        agg[r0*HDIM + c]     = x[0];
                        agg[r0*HDIM + c + 1] = x[1];
                    }
                    if (r0 + 8 < NLOC) {
                        agg[(r0+8)*HDIM + c]     = x[2];
                        agg[(r0+8)*HDIM + c + 1] = x[3];
                    }
                }
        }
        {
            float* w3 = (float*)(smb + OFF_T0);
            for (int i = tid; i < HDIM*FDIM; i += NTHR) w3[i] = W3[i];
        }
        __syncthreads();

        // ---- node phase: kv = tanh(agg/N @ W3 + b3); RK4 update ----
        {
            const float dt = sTs[t+1] - sTs[t];
            const float inv_n = 1.0f / (float)NNODE;
            const float* agg = (float*)(smb + OFF_S);
            const float* w3  = (float*)(smb + OFF_T0);
            const float* sb3 = (float*)(smb + OFF_B3);
            for (int idx = tid; idx < NLOC*FDIM; idx += NTHR) {
                int n = idx >> 6, j = idx & 63;
                const float* ar = agg + n*HDIM;
                float acc = 0.f;
#pragma unroll 8
                for (int h = 0; h < HDIM; ++h)
                    acc = fmaf(ar[h], w3[h*FDIM + j], acc);
                float kv = tanhf(acc * inv_n + sb3[j]);
                int gi = (b*NNODE + rstart + n)*FDIM + j;
                float yv = g_y[gi];
                float yin;
                if (stage == 0)      { g_ksum[gi] = kv;        yin = yv + 0.5f*dt*kv; }
                else if (stage == 1) { g_ksum[gi] += 2.f*kv;   yin = yv + 0.5f*dt*kv; }
                else if (stage == 2) { g_ksum[gi] += 2.f*kv;   yin = yv + dt*kv; }
                else {
                    float yn = yv + dt*(1.f/6.f)*(g_ksum[gi] + kv);
                    g_y[gi] = yn;
                    out[(b*NNODE + rstart + n)*(TSTEPS*FDIM) + (t+1)*FDIM + j] = yn;
                    yin = yn;
                }
                g_ybf[gi] = __float2bfloat16(yin);
            }
        }

        // ---- pair barrier ----
        __syncthreads();
        __threadfence();
        if (tid == 0) {
            atomicAdd(barp, 1);
            const int target = 2*(iter + 1);
            while (*(volatile int*)barp < target) { }
            __threadfence();
        }
        __syncthreads();
    }
}

// ---------------- launcher ----------------
extern "C" void kernel_launch(void* const* d_in, const int* in_sizes, int n_in,
                              void* d_out, int out_size) {
    const float* fp    = (const float*)d_in[0];
    const float* ts    = (const float*)d_in[1];
    const int*   graph = (const int*)d_in[2];
    const float* W1    = (const float*)d_in[3];
    const float* b1    = (const float*)d_in[4];
    const float* W2    = (const float*)d_in[5];
    const float* b2    = (const float*)d_in[6];
    const float* W3    = (const float*)d_in[7];
    const float* b3    = (const float*)d_in[8];
    float* out = (float*)d_out;

    cudaFuncSetAttribute(persist_kernel, cudaFuncAttributeMaxDynamicSharedMemorySize, SMEM_TOTAL);

    prep_kernel<<<256, 256>>>(fp, W1, W2, out);
    sort_kernel<<<NCTA, 32>>>(graph);
    persist_kernel<<<NCTA, NTHR, SMEM_TOTAL>>>(b1, b2, W3, b3, ts, out);
}

// round 17
// speedup vs baseline: 1.4419x; 1.0147x over previous
#include <cuda_runtime.h>
#include <cuda_bf16.h>
#include <cstdint>

#define BATCH 64
#define NNODE 50
#define FDIM 64
#define HDIM 128
#define EDGES 2450
#define TSTEPS 40
#define CHUNK 128
#define MAXROWS 1408
#define MAXCH 11
#define NCTA 128             // 64 batches x 2 halves
#define NTHR 512
#define NLOC 25
#define NSTAGE ((TSTEPS-1)*4)

// ---- smem byte offsets ----
#define OFF_W2  0            // 4 tiles x 16KB = 65536 (W2: k*2+half)
#define OFF_T0  65536        // 32KB: h tile; yA during UV; W3 in node phase
#define OFF_T1  98304        // 32KB: m tile; W1uv staging during UV
#define OFF_UV  131072       // 4 x 17408 = 69632 (U0,V0,U1,V1: 64 rows x 272B)
#define OFF_B1  200704       // 512B: b1 packed bf16x2 (128 u32)
#define OFF_B2  201728       // 1024B: b2 fp32
#define OFF_B3  202752
#define OFF_TS  203008
#define OFF_S   203264       // 2 x 8704 S buffers; reused as agg fp32 [25][128]
#define SMEM_TOTAL 220672

#define SWZ(o) ((o) ^ (((o) >> 3) & 0x70))
#define SSTRIDE 136
#define SBYTES 8704
#define UVT 17408            // 64*272

// ---------------- device scratch ----------------
__device__ float          g_y[BATCH*NNODE*FDIM];
__device__ float          g_ksum[BATCH*NNODE*FDIM];
__device__ __nv_bfloat16  g_ybf[BATCH*NNODE*FDIM];
__device__ __nv_bfloat16  g_Wt[8*8192];     // tiles 0-3: W2; 4-7: W1uv (k*2+uv)
__device__ int            g_rows[NCTA*MAXROWS];
__device__ int            g_nrows[NCTA];
__device__ int            g_bar[BATCH];
__device__ __nv_bfloat16  g_S[NCTA*MAXCH*(SBYTES/2)];   // precomputed S tiles

// ---------------- helpers ----------------
__device__ __forceinline__ void mma16816(float* c, const uint32_t* a, const uint32_t* b) {
    asm volatile(
        "mma.sync.aligned.m16n8k16.row.col.f32.bf16.bf16.f32 "
        "{%0,%1,%2,%3}, {%4,%5,%6,%7}, {%8,%9}, {%0,%1,%2,%3};\n"
        : "+f"(c[0]), "+f"(c[1]), "+f"(c[2]), "+f"(c[3])
        : "r"(a[0]), "r"(a[1]), "r"(a[2]), "r"(a[3]), "r"(b[0]), "r"(b[1]));
}
__device__ __forceinline__ void ldsm4(uint32_t* r, uint32_t addr) {
    asm volatile("ldmatrix.sync.aligned.m8n8.x4.shared.b16 {%0,%1,%2,%3}, [%4];"
                 : "=r"(r[0]), "=r"(r[1]), "=r"(r[2]), "=r"(r[3]) : "r"(addr));
}
__device__ __forceinline__ void ldsm4t(uint32_t* r, uint32_t addr) {
    asm volatile("ldmatrix.sync.aligned.m8n8.x4.trans.shared.b16 {%0,%1,%2,%3}, [%4];"
                 : "=r"(r[0]), "=r"(r[1]), "=r"(r[2]), "=r"(r[3]) : "r"(addr));
}
__device__ __forceinline__ uint32_t smem_u32(const void* p) {
    uint32_t a;
    asm("{ .reg .u64 t; cvta.to.shared.u64 t, %1; cvt.u32.u64 %0, t; }" : "=r"(a) : "l"(p));
    return a;
}
__device__ __forceinline__ uint32_t packbf(float x, float y) {
    __nv_bfloat162 t = __floats2bfloat162_rn(x, y);
    return *reinterpret_cast<uint32_t*>(&t);
}

// ---------------- prep ----------------
__global__ void prep_kernel(const float* __restrict__ fp,
                            const float* __restrict__ W1,
                            const float* __restrict__ W2,
                            float* __restrict__ out) {
    int gsz = gridDim.x * blockDim.x;
    int g0  = blockIdx.x * blockDim.x + threadIdx.x;
    for (int i = g0; i < 8*8192; i += gsz) {
        int tile = i >> 13, rem = i & 8191;
        int n = rem >> 6, kk = rem & 63;
        float v;
        if (tile < 4) {
            int k = tile >> 1, half = tile & 1;
            v = W2[k*16384 + (half*64 + kk)*128 + n];
        } else {
            int tt = tile - 4, k = tt >> 1, uv = tt & 1;
            v = W1[k*16384 + (uv*64 + kk)*128 + n];
        }
        g_Wt[tile*8192 + (SWZ((uint32_t)(n*128 + kk*2)) >> 1)] = __float2bfloat16(v);
    }
    for (int i = g0; i < BATCH*NNODE*FDIM; i += gsz) {
        float v = fp[i];
        g_y[i]   = v;
        g_ybf[i] = __float2bfloat16(v);
        out[(i >> 6)*(TSTEPS*FDIM) + (i & 63)] = v;
    }
    for (int i = g0; i < BATCH; i += gsz) g_bar[i] = 0;
}

// ---------------- sort: stable partition + precomputed S tiles ----------------
__global__ void sort_kernel(const int* __restrict__ graph) {
    const int cta = blockIdx.x;            // b*2 + hb
    const int b = cta >> 1, hb = cta & 1;
    const int ebase = hb * NLOC * 49;
    const int ecnt  = NLOC * 49;
    const int lane = threadIdx.x;
    int* rows = g_rows + cta * MAXROWS;
    int row = 0;
#pragma unroll
    for (int k = 0; k < 2; ++k) {
        for (int i0 = 0; i0 < ecnt; i0 += 32) {
            int i = i0 + lane;
            bool m = false; int meta = 0;
            if (i < ecnt) {
                int e = ebase + i;
                int kk = graph[b*EDGES + e];
                int r = e / 49, j = e - r*49;
                int s = j + (j >= r);
                meta = (kk << 16) | (r << 8) | s;
                m = (kk == k);
            }
            unsigned mask = __ballot_sync(0xffffffffu, m);
            if (m) rows[row + __popc(mask & ((1u << lane) - 1u))] = meta;
            row += __popc(mask);
        }
        int pad = (128 - (row & 127)) & 127;
        for (int i = lane; i < pad; i += 32) rows[row + i] = -1;
        row += pad;
    }
    if (lane == 0) g_nrows[cta] = row;

    // precompute S tiles (stage-invariant receiver patterns)
    const int nch = row >> 7;
    for (int ch = 0; ch < nch; ++ch) {
        __nv_bfloat16* S = g_S + (cta*MAXCH + ch)*(SBYTES/2);
        for (int i = lane; i < SBYTES/4; i += 32)
            ((uint32_t*)S)[i] = 0;
        for (int i = lane; i < CHUNK; i += 32) {
            int v = rows[ch*CHUNK + i];
            if (v >= 0) {
                int rr = ((v >> 8) & 255) - hb*NLOC;
                S[rr*SSTRIDE + i] = __float2bfloat16(1.0f);
            }
        }
    }
}

// gather h tile into T0: h = relu(U_k[s] + V_k[r] + b1[k]) via bf16x2 packed math
// (tid256 in [0,256): row = tid256>>1, half = tid256&1)
__device__ __forceinline__ void gather_h(char* smb, const int* crow,
                                         int tid256, const uint32_t* sB1p) {
    int row = tid256 >> 1, hlf = tid256 & 1;
    int v = crow[row];
    char* tb = smb + OFF_T0 + hlf*16384;
    if (v >= 0) {
        int s = v & 255, r = (v >> 8) & 255, k = v >> 16;
        const uint4* up = (const uint4*)(smb + OFF_UV + (k*2+0)*UVT + s*272 + hlf*128);
        const uint4* vp = (const uint4*)(smb + OFF_UV + (k*2+1)*UVT + r*272 + hlf*128);
        const uint32_t* bp = sB1p + k*64 + hlf*32;
        const __nv_bfloat162 z2 = __floats2bfloat162_rn(0.f, 0.f);
#pragma unroll
        for (int q = 0; q < 8; ++q) {
            uint4 uu = up[q], vv = vp[q];
            const uint32_t* uw = (const uint32_t*)&uu;
            const uint32_t* vw = (const uint32_t*)&vv;
            uint32_t ow[4];
#pragma unroll
            for (int e = 0; e < 4; ++e) {
                __nv_bfloat162 u2 = *(const __nv_bfloat162*)&uw[e];
                __nv_bfloat162 v2 = *(const __nv_bfloat162*)&vw[e];
                __nv_bfloat162 b2 = *(const __nv_bfloat162*)&bp[q*4 + e];
                __nv_bfloat162 h2 = __hmax2(__hadd2(__hadd2(u2, v2), b2), z2);
                ow[e] = *(const uint32_t*)&h2;
            }
            *(uint4*)(tb + SWZ((uint32_t)(row*128 + q*16))) =
                make_uint4(ow[0], ow[1], ow[2], ow[3]);
        }
    } else {
        uint4 z = make_uint4(0,0,0,0);
#pragma unroll
        for (int q = 0; q < 8; ++q)
            *(uint4*)(tb + SWZ((uint32_t)(row*128 + q*16))) = z;
    }
}

// ---------------- persistent fused kernel: 512 threads, 16 warps ----------------
__global__ void __launch_bounds__(NTHR, 1)
persist_kernel(const float* __restrict__ b1f, const float* __restrict__ b2f,
               const float* __restrict__ W3,  const float* __restrict__ b3f,
               const float* __restrict__ tsp, float* __restrict__ out) {
    extern __shared__ char smb[];
    const int tid  = threadIdx.x;
    const int lane = tid & 31, wid = tid >> 5;   // 16 warps
    const int cta  = blockIdx.x;
    const int b = cta >> 1, hb = cta & 1;
    const int rstart = hb * NLOC;
    int* const barp = &g_bar[b];

    // ---- one-time: W2 (64KB), biases (b1 packed bf16x2), ts ----
    {
        const uint4* src = reinterpret_cast<const uint4*>(g_Wt);
        uint4* dst = reinterpret_cast<uint4*>(smb + OFF_W2);
        for (int i = tid; i < 65536/16; i += NTHR) dst[i] = src[i];
    }
    if (tid < 128)
        ((uint32_t*)(smb + OFF_B1))[tid] = packbf(b1f[2*tid], b1f[2*tid + 1]);
    if (tid >= 128 && tid < 384)
        ((float*)(smb + OFF_B2))[tid - 128] = b2f[tid - 128];
    if (tid < 64) ((float*)(smb + OFF_B3))[tid] = b3f[tid];
    if (tid < TSTEPS) ((float*)(smb + OFF_TS))[tid] = tsp[tid];

    const uint32_t* sB1p = (const uint32_t*)(smb + OFF_B1);
    const float* sB2 = (float*)(smb + OFF_B2);
    const float* sTs = (float*)(smb + OFF_TS);

    const int nch = g_nrows[cta] >> 7;
    const int* __restrict__ rows = g_rows + cta * MAXROWS;
    const __nv_bfloat16* __restrict__ Sg = g_S + cta*MAXCH*(SBYTES/2);

    // GEMM2 warp tiling: 4M x 4N of 32x32 tiles
    const int wm = (wid & 3) * 32;
    const int wn = (wid >> 2) * 32;
    const int g = lane >> 2, tig = lane & 3;
    const int li = lane & 7, lm = lane >> 3;
    const int aRow = (lm & 1)*8 + li;
    const int aK16 = (lm >> 1) * 16;
    const int bRow = (lm >> 1)*8 + li;
    const int bK16 = (lm & 1) * 16;

    const uint32_t uT0 = smem_u32(smb + OFF_T0);
    const uint32_t uT1 = smem_u32(smb + OFF_T1);
    const uint32_t uW2 = smem_u32(smb + OFF_W2);
    const uint32_t uS  = smem_u32(smb + OFF_S);

    // agg-MMA (warps 0-7): warp owns m cols wid*16..+15
    const uint32_t aggHalf = (wid >= 4) ? 16384u : 0u;
    const uint32_t aggRowL = (uint32_t)((lm & 1)*8 + li);
    const uint32_t aggColL = (uint32_t)(((wid & 3)*16 + (lm >> 1)*8) * 2);
    const uint32_t sAbase = (uint32_t)(g*(SSTRIDE*2) + 2*tig*2);

    // UV pass mapping: uv = wid>>3 (0=U send, 1=V recv), nq8 = wid&7 (16-col group)
    const int uv  = wid >> 3;
    const int nq8 = wid & 7;

    for (int iter = 0; iter < NSTAGE; ++iter) {
        const int t = iter >> 2, stage = iter & 3;

        // ---- stage setup: yA tile -> T0 (64x64 bf16 SW128) ----
        {
            const uint4* src = (const uint4*)(g_ybf + b*NNODE*FDIM);
            for (int i = tid; i < 512; i += NTHR) {
                int row = i >> 3, q = i & 7;
                uint4 val = make_uint4(0,0,0,0);
                if (row < NNODE) val = src[row*8 + q];
                *(uint4*)(smb + OFF_T0 + SWZ((uint32_t)(row*128 + q*16))) = val;
            }
        }
        __syncthreads();

        // ---- UV passes: one per k; warps 0-7 compute U_k, warps 8-15 V_k ----
#pragma unroll
        for (int kpass = 0; kpass < 2; ++kpass) {
            {
                const uint4* src = (const uint4*)(g_Wt + (4 + kpass*2)*8192);
                uint4* dst = (uint4*)(smb + OFF_T1);
                for (int i = tid; i < 2048; i += NTHR) dst[i] = src[i];
            }
            __syncthreads();
            {
                float C[8][4];
#pragma unroll
                for (int i = 0; i < 8; ++i) { C[i][0]=0.f; C[i][1]=0.f; C[i][2]=0.f; C[i][3]=0.f; }
#pragma unroll
                for (int kb = 0; kb < 4; ++kb) {
                    uint32_t a[4][4];
#pragma unroll
                    for (int mt = 0; mt < 4; ++mt) {
                        uint32_t o = (uint32_t)((mt*16 + aRow)*128) + (uint32_t)(kb*32) + aK16;
                        ldsm4(a[mt], uT0 + SWZ(o));
                    }
                    uint32_t bf[4];
                    {
                        uint32_t o = (uint32_t)((nq8*16 + bRow)*128) + (uint32_t)(kb*32) + bK16;
                        ldsm4(bf, uT1 + (uint32_t)(uv*16384) + SWZ(o));
                    }
#pragma unroll
                    for (int mt = 0; mt < 4; ++mt)
#pragma unroll
                        for (int nt = 0; nt < 2; ++nt)
                            mma16816(C[mt*2 + nt], a[mt], &bf[nt*2]);
                }
                char* base = smb + OFF_UV + (kpass*2 + uv)*UVT;
#pragma unroll
                for (int mt = 0; mt < 4; ++mt)
#pragma unroll
                    for (int nt = 0; nt < 2; ++nt) {
                        int r0 = mt*16 + g, r1 = r0 + 8;
                        int c = nq8*16 + nt*8 + 2*tig;
                        float* x = C[mt*2 + nt];
                        *(uint32_t*)(base + r0*272 + c*2) = packbf(x[0], x[1]);
                        *(uint32_t*)(base + r1*272 + c*2) = packbf(x[2], x[3]);
                    }
            }
            __syncthreads();
        }

        // ---- prologue: gather h chunk0 -> T0; load S[0] -> buf0 ----
        if (tid < 256) gather_h(smb, rows, tid, sB1p);
        else {
            const uint4* src = (const uint4*)Sg;
            uint4* dst = (uint4*)(smb + OFF_S);
            for (int i = tid - 256; i < SBYTES/16; i += 256) dst[i] = src[i];
        }
        float Ca[2][2][4];
#pragma unroll
        for (int i = 0; i < 2; ++i)
#pragma unroll
            for (int j = 0; j < 2; ++j) { Ca[i][j][0]=0.f; Ca[i][j][1]=0.f; Ca[i][j][2]=0.f; Ca[i][j][3]=0.f; }
        __syncthreads();

        // ---- chunk loop: h in T0, m in T1; 2 syncs/chunk ----
        for (int ch = 0; ch < nch; ++ch) {
            const int p = ch & 1;
            const int k = rows[ch*CHUNK] >> 16;
            const uint32_t w2base = uW2 + (uint32_t)(k*32768);

            // ==== interval 1: load S[ch+1] -> buf[1-p]; GEMM2 (A=h in T0) -> m in T1 ====
            if (ch + 1 < nch) {
                const uint4* src = (const uint4*)(Sg + (ch+1)*(SBYTES/2));
                uint4* dst = (uint4*)(smb + OFF_S + (1-p)*SBYTES);
                for (int i = tid; i < SBYTES/16; i += NTHR) dst[i] = src[i];
            }
            float C[8][4];
#pragma unroll
            for (int i = 0; i < 8; ++i) { C[i][0]=0.f; C[i][1]=0.f; C[i][2]=0.f; C[i][3]=0.f; }
#pragma unroll
            for (int kb = 0; kb < 8; ++kb) {
                const uint32_t half16 = (uint32_t)((kb >> 2) * 16384);
                const uint32_t kgrp = (uint32_t)((kb & 3) * 32);
                uint32_t a[2][4];
#pragma unroll
                for (int mt = 0; mt < 2; ++mt) {
                    uint32_t o = (uint32_t)((wm + mt*16 + aRow)*128) + kgrp + aK16;
                    ldsm4(a[mt], uT0 + half16 + SWZ(o));
                }
                uint32_t bf[2][4];
#pragma unroll
                for (int nt2 = 0; nt2 < 2; ++nt2) {
                    uint32_t o = (uint32_t)((wn + nt2*16 + bRow)*128) + kgrp + bK16;
                    ldsm4(bf[nt2], w2base + half16 + SWZ(o));
                }
#pragma unroll
                for (int mt = 0; mt < 2; ++mt)
#pragma unroll
                    for (int nt = 0; nt < 4; ++nt)
                        mma16816(C[mt*4 + nt], a[mt], &bf[nt >> 1][(nt & 1)*2]);
            }
            {
                char* tb = smb + OFF_T1 + ((wn >= 64) ? 16384 : 0);
#pragma unroll
                for (int mt = 0; mt < 2; ++mt)
#pragma unroll
                    for (int nt = 0; nt < 4; ++nt) {
                        int r0 = wm + mt*16 + g, r1 = r0 + 8;
                        int c = wn + nt*8 + 2*tig;
                        float b0v = sB2[k*HDIM + c], b1v = sB2[k*HDIM + c + 1];
                        float* x = C[mt*4 + nt];
                        uint32_t cb = (uint32_t)((c & 63)*2);
                        *(uint32_t*)(tb + SWZ((uint32_t)(r0*128) + cb)) =
                            packbf(fmaxf(x[0]+b0v,0.f), fmaxf(x[1]+b1v,0.f));
                        *(uint32_t*)(tb + SWZ((uint32_t)(r1*128) + cb)) =
                            packbf(fmaxf(x[2]+b0v,0.f), fmaxf(x[3]+b1v,0.f));
                    }
            }
            __syncthreads();

            // ==== interval 2: warps 0-7 agg MMA (S[p] @ m) ; warps 8-15 gather ch+1 ====
            if (wid < 8) {
                const uint32_t uSp = uS + (uint32_t)(p*SBYTES);
#pragma unroll
                for (int kb = 0; kb < 8; ++kb) {
                    uint32_t a[2][4];
#pragma unroll
                    for (int mg = 0; mg < 2; ++mg) {
                        uint32_t ao = uSp + sAbase + (uint32_t)(mg*16*(SSTRIDE*2) + kb*32);
                        asm volatile("ld.shared.b32 %0, [%1];" : "=r"(a[mg][0]) : "r"(ao));
                        asm volatile("ld.shared.b32 %0, [%1];" : "=r"(a[mg][1]) : "r"(ao + 8*(SSTRIDE*2)));
                        asm volatile("ld.shared.b32 %0, [%1];" : "=r"(a[mg][2]) : "r"(ao + 16));
                        asm volatile("ld.shared.b32 %0, [%1];" : "=r"(a[mg][3]) : "r"(ao + 8*(SSTRIDE*2) + 16));
                    }
                    uint32_t bf[4];
                    uint32_t o = (uint32_t)((kb*16 + aggRowL)*128) + aggColL;
                    ldsm4t(bf, uT1 + aggHalf + SWZ(o));
                    mma16816(Ca[0][0], a[0], bf);
                    mma16816(Ca[0][1], a[0], bf + 2);
                    mma16816(Ca[1][0], a[1], bf);
                    mma16816(Ca[1][1], a[1], bf + 2);
                }
            } else if (ch + 1 < nch) {
                gather_h(smb, rows + (ch+1)*CHUNK, tid - 256, sB1p);
            }
            __syncthreads();
        }

        // ---- Ca -> agg (S region, warps 0-7), stage W3 -> T0 ----
        if (wid < 8) {
            float* agg = (float*)(smb + OFF_S);
#pragma unroll
            for (int mg = 0; mg < 2; ++mg)
#pragma unroll
                for (int n8 = 0; n8 < 2; ++n8) {
                    int r0 = mg*16 + g;
                    int c = wid*16 + n8*8 + 2*tig;
                    float* x = Ca[mg][n8];
                    if (r0 < NLOC) {
                        agg[r0*HDIM + c]     = x[0];
                        agg[r0*HDIM + c + 1] = x[1];
                    }
                    if (r0 + 8 < NLOC) {
                        agg[(r0+8)*HDIM + c]     = x[2];
                        agg[(r0+8)*HDIM + c + 1] = x[3];
                    }
                }
        }
        {
            float* w3 = (float*)(smb + OFF_T0);
            for (int i = tid; i < HDIM*FDIM; i += NTHR) w3[i] = W3[i];
        }
        __syncthreads();

        // ---- node phase: kv = tanh(agg/N @ W3 + b3); RK4 update ----
        {
            const float dt = sTs[t+1] - sTs[t];
            const float inv_n = 1.0f / (float)NNODE;
            const float* agg = (float*)(smb + OFF_S);
            const float* w3  = (float*)(smb + OFF_T0);
            const float* sb3 = (float*)(smb + OFF_B3);
            for (int idx = tid; idx < NLOC*FDIM; idx += NTHR) {
                int n = idx >> 6, j = idx & 63;
                const float* ar = agg + n*HDIM;
                float acc = 0.f;
#pragma unroll 8
                for (int h = 0; h < HDIM; ++h)
                    acc = fmaf(ar[h], w3[h*FDIM + j], acc);
                float kv = tanhf(acc * inv_n + sb3[j]);
                int gi = (b*NNODE + rstart + n)*FDIM + j;
                float yv = g_y[gi];
                float yin;
                if (stage == 0)      { g_ksum[gi] = kv;        yin = yv + 0.5f*dt*kv; }
                else if (stage == 1) { g_ksum[gi] += 2.f*kv;   yin = yv + 0.5f*dt*kv; }
                else if (stage == 2) { g_ksum[gi] += 2.f*kv;   yin = yv + dt*kv; }
                else {
                    float yn = yv + dt*(1.f/6.f)*(g_ksum[gi] + kv);
                    g_y[gi] = yn;
                    out[(b*NNODE + rstart + n)*(TSTEPS*FDIM) + (t+1)*FDIM + j] = yn;
                    yin = yn;
                }
                g_ybf[gi] = __float2bfloat16(yin);
            }
        }

        // ---- pair barrier ----
        __syncthreads();
        __threadfence();
        if (tid == 0) {
            atomicAdd(barp, 1);
            const int target = 2*(iter + 1);
            while (*(volatile int*)barp < target) { }
            __threadfence();
        }
        __syncthreads();
    }
}

// ---------------- launcher ----------------
extern "C" void kernel_launch(void* const* d_in, const int* in_sizes, int n_in,
                              void* d_out, int out_size) {
    const float* fp    = (const float*)d_in[0];
    const float* ts    = (const float*)d_in[1];
    const int*   graph = (const int*)d_in[2];
    const float* W1    = (const float*)d_in[3];
    const float* b1    = (const float*)d_in[4];
    const float* W2    = (const float*)d_in[5];
    const float* b2    = (const float*)d_in[6];
    const float* W3    = (const float*)d_in[7];
    const float* b3    = (const float*)d_in[8];
    float* out = (float*)d_out;

    cudaFuncSetAttribute(persist_kernel, cudaFuncAttributeMaxDynamicSharedMemorySize, SMEM_TOTAL);

    prep_kernel<<<256, 256>>>(fp, W1, W2, out);
    sort_kernel<<<NCTA, 32>>>(graph);
    persist_kernel<<<NCTA, NTHR, SMEM_TOTAL>>>(b1, b2, W3, b3, ts, out);
}